// round 3
// baseline (speedup 1.0000x reference)
#include <cuda_runtime.h>
#include <cuda_bf16.h>
#include <math.h>
#include <stdint.h>

#define BB 32
#define SS 1024
#define HH 768
#define EE 128
#define WW 8
#define PP 512
#define NTT 5
#define NRR 9
#define DD1 128
#define HEADS1 2
#define DD2 64
#define RDD 32
#define F1 256  // HEADS1*DD1

// ---------------- scratch ----------------
static __device__ float g_x0[BB*EE*HH];
static __device__ float g_h1[BB*EE*F1];
static __device__ float g_alpha1[BB*HEADS1*EE*EE];
static __device__ float g_o1[BB*EE*F1];
static __device__ float g_x1[BB*EE*F1];
static __device__ float g_h2[BB*EE*DD2];
static __device__ float g_alpha2[BB*EE*EE];
static __device__ float g_o2[BB*EE*DD2];
static __device__ float g_x2[BB*EE*DD2];
static __device__ float g_p[2*BB*EE*256];
static __device__ float g_cls[BB*256];
static __device__ float g_rel[NRR*256];

// ---------------- 1. entity pooling + type embedding ----------------
__global__ void pool_kernel(const float* __restrict__ seq,
                            const int* __restrict__ starts,
                            const int* __restrict__ type_ids,
                            const float* __restrict__ temb,
                            float* __restrict__ x0) {
    int be = blockIdx.x;
    int b = be >> 7;
    int t = threadIdx.x;                 // 256 threads
    __shared__ float toks[WW*HH];
    __shared__ float colsum[HH];
    __shared__ float logits[WW];

    int start = starts[be];
    const float* base = seq + ((size_t)b*SS + start)*HH;
    for (int i = t; i < WW*HH; i += 256) toks[i] = base[i];
    __syncthreads();

    for (int h = t; h < HH; h += 256) {
        float cs = 0.f;
        #pragma unroll
        for (int w = 0; w < WW; w++) cs += toks[w*HH + h];
        colsum[h] = cs;
    }
    __syncthreads();

    int warp = t >> 5, lane = t & 31;
    {
        float acc = 0.f;
        for (int h = lane; h < HH; h += 32) acc += toks[warp*HH + h] * colsum[h];
        #pragma unroll
        for (int off = 16; off > 0; off >>= 1) acc += __shfl_xor_sync(0xffffffffu, acc, off);
        if (lane == 0) logits[warp] = acc * 0.125f;
    }
    __syncthreads();

    float m = logits[0];
    #pragma unroll
    for (int w = 1; w < WW; w++) m = fmaxf(m, logits[w]);
    float ex[WW]; float sum = 0.f;
    #pragma unroll
    for (int w = 0; w < WW; w++) { ex[w] = __expf(logits[w] - m); sum += ex[w]; }
    float inv = 1.f / sum;

    int type = type_ids[be];
    const float* te = temb + (size_t)type*HH;
    for (int h = t; h < HH; h += 256) {
        float p = 0.f;
        #pragma unroll
        for (int w = 0; w < WW; w++) p += ex[w] * toks[w*HH + h];
        x0[(size_t)be*HH + h] = p*inv + te[h];
    }
}

// ---------------- bf16x3 tensor-core GEMM ----------------
// C = A @ B fp32 in/out via bf16 hi/lo split (3 MMAs, rel err ~3e-5).
// Block tile 64x64, K-chunk 32. 8 warps = 2(m) x 4(n), warp tile 32x16.
__device__ __forceinline__ void mma16(float* d, const uint32_t* a, const uint32_t* b) {
    asm volatile(
        "mma.sync.aligned.m16n8k16.row.col.f32.bf16.bf16.f32 "
        "{%0,%1,%2,%3},{%4,%5,%6,%7},{%8,%9},{%0,%1,%2,%3};"
        : "+f"(d[0]), "+f"(d[1]), "+f"(d[2]), "+f"(d[3])
        : "r"(a[0]), "r"(a[1]), "r"(a[2]), "r"(a[3]), "r"(b[0]), "r"(b[1]));
}
// pack (v0 -> low half / k even, v1 -> high half / k odd); lo = residual
__device__ __forceinline__ void split2(float v0, float v1, uint32_t& h, uint32_t& l) {
    uint32_t hp, lp;
    asm("cvt.rn.bf16x2.f32 %0, %1, %2;" : "=r"(hp) : "f"(v1), "f"(v0));
    float h0 = __uint_as_float(hp << 16);
    float h1 = __uint_as_float(hp & 0xffff0000u);
    asm("cvt.rn.bf16x2.f32 %0, %1, %2;" : "=r"(lp) : "f"(v1 - h1), "f"(v0 - h0));
    h = hp; l = lp;
}

#define SA 20   // A smem stride (u32): banks 20g+ti distinct for g=0..7,ti=0..3
#define SBp 72  // B smem stride (u32): banks 8*k2+g distinct

__global__ __launch_bounds__(256) void bf16_gemm(
        const float* __restrict__ A, const float* __restrict__ Bm,
        float* __restrict__ C,
        int M, int N, int K, int lda, int ldb, int ldc,
        int Hh, long strA, long sBb, long sBh, long sCb, long sCh) {
    int bz = blockIdx.z;
    int bb = bz / Hh, hh = bz - bb*Hh;
    A  += (long)bz * strA;
    Bm += (long)bb * sBb + (long)hh * sBh;
    C  += (long)bb * sCb + (long)hh * sCh;

    // A: [row 0..63][k2 0..15] packed bf16x2 (k even low, k odd high)
    __shared__ uint32_t AsH[64][SA], AsL[64][SA];
    // B: [k2 0..15][n 0..63]
    __shared__ uint32_t BsH[16][SBp], BsL[16][SBp];

    int tid = threadIdx.x;
    int wid = tid >> 5, lane = tid & 31;
    int g = lane >> 2, ti = lane & 3;
    int warp_m = wid >> 2;
    int warp_n = wid & 3;
    int m0 = blockIdx.y * 64, n0 = blockIdx.x * 64;

    float acc[2][2][4] = {};

    for (int kc = 0; kc < K; kc += 32) {
        // ---- A chunk: 64x32 floats, 2 float4 per thread ----
        #pragma unroll
        for (int i = 0; i < 2; i++) {
            int idx = tid + i*256;
            int row = idx >> 3, q = idx & 7;          // k = q*4
            float4 av = *(const float4*)(A + (size_t)(m0 + row)*lda + kc + q*4);
            uint32_t h0, l0, h1, l1;
            split2(av.x, av.y, h0, l0);
            split2(av.z, av.w, h1, l1);
            AsH[row][2*q]   = h0; AsH[row][2*q+1] = h1;
            AsL[row][2*q]   = l0; AsL[row][2*q+1] = l1;
        }
        // ---- B chunk: 32x64 floats, thread loads 2 rows x 4 cols ----
        {
            int r = tid >> 4;                 // k-pair 0..15
            int n4 = (tid & 15) * 4;
            float4 b0v = *(const float4*)(Bm + (size_t)(kc + 2*r)*ldb + n0 + n4);
            float4 b1v = *(const float4*)(Bm + (size_t)(kc + 2*r + 1)*ldb + n0 + n4);
            uint32_t h, l;
            split2(b0v.x, b1v.x, h, l); BsH[r][n4+0] = h; BsL[r][n4+0] = l;
            split2(b0v.y, b1v.y, h, l); BsH[r][n4+1] = h; BsL[r][n4+1] = l;
            split2(b0v.z, b1v.z, h, l); BsH[r][n4+2] = h; BsL[r][n4+2] = l;
            split2(b0v.w, b1v.w, h, l); BsH[r][n4+3] = h; BsL[r][n4+3] = l;
        }
        __syncthreads();

        #pragma unroll
        for (int s = 0; s < 2; s++) {
            int ab = s*8;                      // A u32 base
            uint32_t aH[2][4], aL[2][4], bH[2][2], bL[2][2];
            #pragma unroll
            for (int mt = 0; mt < 2; mt++) {
                int rm = warp_m*32 + mt*16;
                aH[mt][0] = AsH[rm + g    ][ab + ti    ];
                aH[mt][1] = AsH[rm + g + 8][ab + ti    ];
                aH[mt][2] = AsH[rm + g    ][ab + ti + 4];
                aH[mt][3] = AsH[rm + g + 8][ab + ti + 4];
                aL[mt][0] = AsL[rm + g    ][ab + ti    ];
                aL[mt][1] = AsL[rm + g + 8][ab + ti    ];
                aL[mt][2] = AsL[rm + g    ][ab + ti + 4];
                aL[mt][3] = AsL[rm + g + 8][ab + ti + 4];
            }
            #pragma unroll
            for (int nt = 0; nt < 2; nt++) {
                int cn = warp_n*16 + nt*8;
                bH[nt][0] = BsH[ab + ti    ][cn + g];
                bH[nt][1] = BsH[ab + ti + 4][cn + g];
                bL[nt][0] = BsL[ab + ti    ][cn + g];
                bL[nt][1] = BsL[ab + ti + 4][cn + g];
            }
            #pragma unroll
            for (int mt = 0; mt < 2; mt++)
                #pragma unroll
                for (int nt = 0; nt < 2; nt++) {
                    mma16(acc[mt][nt], aH[mt], bL[nt]);
                    mma16(acc[mt][nt], aL[mt], bH[nt]);
                    mma16(acc[mt][nt], aH[mt], bH[nt]);
                }
        }
        __syncthreads();
    }

    #pragma unroll
    for (int mt = 0; mt < 2; mt++) {
        int rm = m0 + warp_m*32 + mt*16;
        #pragma unroll
        for (int nt = 0; nt < 2; nt++) {
            int cn = n0 + warp_n*16 + nt*8;
            float* c0 = C + (size_t)(rm + g)*ldc + cn + 2*ti;
            float* c2 = C + (size_t)(rm + g + 8)*ldc + cn + 2*ti;
            c0[0] = acc[mt][nt][0]; c0[1] = acc[mt][nt][1];
            c2[0] = acc[mt][nt][2]; c2[1] = acc[mt][nt][3];
        }
    }
}

// ---------------- fused GAT attention: s/d dots + leaky + softmax ----------------
// one block per (b, head); 128 threads.
__global__ void attn_kernel(const float* __restrict__ h,
                            const float* __restrict__ a_src,
                            const float* __restrict__ a_dst,
                            float* __restrict__ alpha,
                            int F, int D, int Hh) {
    int bh = blockIdx.x;
    int b = bh / Hh, head = bh - b*Hh;
    const float* hb = h + (size_t)b*EE*F + head*D;
    const float* asr = a_src + head*D;
    const float* ads = a_dst + head*D;
    __shared__ float s_sh[EE], d_sh[EE];
    int wid = threadIdx.x >> 5, lane = threadIdx.x & 31;
    int nq = D >> 5;

    for (int e = wid; e < EE; e += 4) {
        float as = 0.f, ad = 0.f;
        for (int q = 0; q < nq; q++) {
            int c = lane + q*32;
            float v = hb[(size_t)e*F + c];
            as += v * asr[c];
            ad += v * ads[c];
        }
        #pragma unroll
        for (int off = 16; off > 0; off >>= 1) {
            as += __shfl_xor_sync(0xffffffffu, as, off);
            ad += __shfl_xor_sync(0xffffffffu, ad, off);
        }
        if (lane == 0) { s_sh[e] = as; d_sh[e] = ad; }
    }
    __syncthreads();

    float* ab = alpha + (size_t)bh*EE*EE;
    for (int i = wid; i < EE; i += 4) {
        float di = d_sh[i];
        float ev[4]; float m = -1e30f;
        #pragma unroll
        for (int q = 0; q < 4; q++) {
            float e = di + s_sh[lane + q*32];
            e = (e >= 0.f) ? e : 0.2f*e;
            ev[q] = e;
            m = fmaxf(m, e);
        }
        #pragma unroll
        for (int off = 16; off > 0; off >>= 1) m = fmaxf(m, __shfl_xor_sync(0xffffffffu, m, off));
        float sum = 0.f;
        #pragma unroll
        for (int q = 0; q < 4; q++) { ev[q] = __expf(ev[q] - m); sum += ev[q]; }
        #pragma unroll
        for (int off = 16; off > 0; off >>= 1) sum += __shfl_xor_sync(0xffffffffu, sum, off);
        float inv = 1.f / sum;
        #pragma unroll
        for (int q = 0; q < 4; q++)
            ab[(size_t)i*EE + lane + q*32] = ev[q]*inv;
    }
}

// ---------------- bias + layernorm + elu ----------------
__global__ void lnelu_kernel(const float* __restrict__ in,
                             const float* __restrict__ bias,
                             const float* __restrict__ g,
                             const float* __restrict__ bt,
                             float* __restrict__ out, int F) {
    int row = blockIdx.x;
    int t = threadIdx.x;
    float v = in[(size_t)row*F + t] + bias[t];
    float s = v, s2 = v*v;
    #pragma unroll
    for (int off = 16; off > 0; off >>= 1) {
        s  += __shfl_xor_sync(0xffffffffu, s,  off);
        s2 += __shfl_xor_sync(0xffffffffu, s2, off);
    }
    __shared__ float ws[8], ws2[8];
    int wid = t >> 5, lane = t & 31, nw = F >> 5;
    if (lane == 0) { ws[wid] = s; ws2[wid] = s2; }
    __syncthreads();
    float S = 0.f, S2 = 0.f;
    for (int k = 0; k < nw; k++) { S += ws[k]; S2 += ws2[k]; }
    float mean = S / F;
    float var = S2 / F - mean*mean;
    float y = (v - mean) * rsqrtf(var + 1e-5f) * g[t] + bt[t];
    out[(size_t)row*F + t] = (y > 0.f) ? y : expm1f(y);
}

// ---------------- misc: cls projection (+br1) and rel-type projection ----------------
__global__ void misc_kernel(const float* __restrict__ seq,
                            const float* __restrict__ remb,
                            const float* __restrict__ Wr1,
                            const float* __restrict__ br1,
                            float* __restrict__ clsp,
                            float* __restrict__ relp) {
    int blk = blockIdx.x;
    int c = threadIdx.x;  // 256
    if (blk < BB) {
        int b = blk;
        __shared__ float cls[HH];
        for (int h = c; h < HH; h += 256) cls[h] = seq[(size_t)b*SS*HH + h];
        __syncthreads();
        float acc = br1[c];
        const float* w = Wr1 + (size_t)160*256 + c;
        for (int h = 0; h < HH; h++) acc += cls[h] * w[(size_t)h*256];
        clsp[b*256 + c] = acc;
    } else {
        int r = blk - BB;
        __shared__ float rv[RDD];
        if (c < RDD) rv[c] = remb[r*RDD + c];
        __syncthreads();
        float acc = 0.f;
        #pragma unroll
        for (int k = 0; k < RDD; k++) acc += rv[k] * Wr1[(size_t)(128 + k)*256 + c];
        relp[r*256 + c] = acc;
    }
}

// ---------------- final pair scores ----------------
__global__ void pair_kernel(const int* __restrict__ pidx,
                            const int* __restrict__ rids,
                            const float* __restrict__ p1,
                            const float* __restrict__ p2,
                            const float* __restrict__ relp,
                            const float* __restrict__ clsp,
                            const float* __restrict__ Wr2,
                            const float* __restrict__ br2,
                            float* __restrict__ out) {
    int g = (blockIdx.x * blockDim.x + threadIdx.x) >> 5;
    int lane = threadIdx.x & 31;
    int b = g / PP, p = g % PP;
    int pi = pidx[(b*PP + p)*2 + 0];
    int pj = pidx[(b*PP + p)*2 + 1];
    int r  = rids[b*PP + p];
    const float* a1 = p1 + (size_t)(b*EE + pi)*256;
    const float* a2 = p2 + (size_t)(b*EE + pj)*256;
    const float* ar = relp + r*256;
    const float* ac = clsp + b*256;
    float acc = 0.f;
    #pragma unroll
    for (int q = 0; q < 8; q++) {
        int c = lane + q*32;
        float v = a1[c] + a2[c] + ar[c] + ac[c];
        v = fmaxf(v, 0.f);
        acc += v * Wr2[c];
    }
    #pragma unroll
    for (int off = 16; off > 0; off >>= 1) acc += __shfl_xor_sync(0xffffffffu, acc, off);
    if (lane == 0) out[b*PP + p] = acc + br2[0];
}

// ---------------- launch ----------------
extern "C" void kernel_launch(void* const* d_in, const int* in_sizes, int n_in,
                              void* d_out, int out_size) {
    const float* seq      = (const float*)d_in[0];
    const int*   starts   = (const int*)  d_in[1];
    const int*   type_ids = (const int*)  d_in[2];
    const int*   pair_idx = (const int*)  d_in[3];
    const int*   rel_ids  = (const int*)  d_in[4];
    const float* temb     = (const float*)d_in[5];
    const float* remb     = (const float*)d_in[6];
    const float* W1       = (const float*)d_in[7];
    const float* a_src1   = (const float*)d_in[8];
    const float* a_dst1   = (const float*)d_in[9];
    const float* b1       = (const float*)d_in[10];
    const float* ln1_g    = (const float*)d_in[11];
    const float* ln1_b    = (const float*)d_in[12];
    const float* W2       = (const float*)d_in[13];
    const float* a_src2   = (const float*)d_in[14];
    const float* a_dst2   = (const float*)d_in[15];
    const float* b2       = (const float*)d_in[16];
    const float* ln2_g    = (const float*)d_in[17];
    const float* ln2_b    = (const float*)d_in[18];
    const float* Wr1      = (const float*)d_in[19];
    const float* br1      = (const float*)d_in[20];
    const float* Wr2      = (const float*)d_in[21];
    const float* br2      = (const float*)d_in[22];
    float* out = (float*)d_out;

    float *x0, *h1, *al1, *o1, *x1, *h2, *al2, *o2, *x2, *pbuf, *clsp, *relp;
    cudaGetSymbolAddress((void**)&x0,  g_x0);
    cudaGetSymbolAddress((void**)&h1,  g_h1);
    cudaGetSymbolAddress((void**)&al1, g_alpha1);
    cudaGetSymbolAddress((void**)&o1,  g_o1);
    cudaGetSymbolAddress((void**)&x1,  g_x1);
    cudaGetSymbolAddress((void**)&h2,  g_h2);
    cudaGetSymbolAddress((void**)&al2, g_alpha2);
    cudaGetSymbolAddress((void**)&o2,  g_o2);
    cudaGetSymbolAddress((void**)&x2,  g_x2);
    cudaGetSymbolAddress((void**)&pbuf, g_p);
    cudaGetSymbolAddress((void**)&clsp, g_cls);
    cudaGetSymbolAddress((void**)&relp, g_rel);
    float* p1 = pbuf;
    float* p2 = pbuf + (size_t)BB*EE*256;

    // 1. pooling + type emb
    pool_kernel<<<BB*EE, 256>>>(seq, starts, type_ids, temb, x0);

    // 2. h1 = x0 @ W1  (4096,768)@(768,256)
    bf16_gemm<<<dim3(4, 64, 1), 256>>>(x0, W1, h1, BB*EE, F1, HH,
                                       HH, F1, F1, 1, 0, 0, 0, 0, 0);

    // 3. attn1: s/d + softmax fused
    attn_kernel<<<BB*HEADS1, 128>>>(h1, a_src1, a_dst1, al1, F1, DD1, HEADS1);

    // 4. o1 = alpha1 @ h1 per (b,head)
    bf16_gemm<<<dim3(2, 2, BB*HEADS1), 256>>>(al1, h1, o1, EE, DD1, EE,
                                              EE, F1, F1, HEADS1,
                                              (long)EE*EE, (long)EE*F1, DD1,
                                              (long)EE*F1, DD1);

    // 5. x1 = elu(ln(o1 + b1))
    lnelu_kernel<<<BB*EE, F1>>>(o1, b1, ln1_g, ln1_b, x1, F1);

    // 6. h2 = x1 @ W2  (4096,256)@(256,64)
    bf16_gemm<<<dim3(1, 64, 1), 256>>>(x1, W2, h2, BB*EE, DD2, F1,
                                       F1, DD2, DD2, 1, 0, 0, 0, 0, 0);

    // 7. attn2
    attn_kernel<<<BB, 128>>>(h2, a_src2, a_dst2, al2, DD2, DD2, 1);

    // 8. o2 = alpha2 @ h2 per b
    bf16_gemm<<<dim3(1, 2, BB), 256>>>(al2, h2, o2, EE, DD2, EE,
                                       EE, DD2, DD2, 1,
                                       (long)EE*EE, (long)EE*DD2, 0,
                                       (long)EE*DD2, 0);

    // 9. x2 = elu(ln(o2 + b2))
    lnelu_kernel<<<BB*EE, DD2>>>(o2, b2, ln2_g, ln2_b, x2, DD2);

    // 10. pair projections p1/p2 in one batched launch (z=2 selects weight slice)
    bf16_gemm<<<dim3(4, 64, 2), 256>>>(x2, Wr1, p1, BB*EE, 256, DD2,
                                       DD2, 256, 256, 2,
                                       0, 0, (long)64*256, 0, (long)BB*EE*256);

    // 11. cls (+br1) and rel projections
    misc_kernel<<<BB + NRR, 256>>>(seq, remb, Wr1, br1, clsp, relp);

    // 12. pair scores
    pair_kernel<<<(BB*PP)/8, 256>>>(pair_idx, rel_ids, p1, p2, relp, clsp,
                                    Wr2, br2, out);
}

// round 4
// speedup vs baseline: 1.3257x; 1.3257x over previous
#include <cuda_runtime.h>
#include <cuda_bf16.h>
#include <math.h>
#include <stdint.h>

#define BB 32
#define SS 1024
#define HH 768
#define EE 128
#define WW 8
#define PP 512
#define NTT 5
#define NRR 9
#define DD1 128
#define HEADS1 2
#define DD2 64
#define RDD 32
#define F1 256  // HEADS1*DD1

// ---------------- scratch ----------------
static __device__ float g_x0[BB*EE*HH];
static __device__ float g_h1[BB*EE*F1];
static __device__ float g_s1[BB*HEADS1*EE];
static __device__ float g_d1[BB*HEADS1*EE];
static __device__ float g_alpha1[BB*HEADS1*EE*EE];
static __device__ float g_o1[BB*EE*F1];
static __device__ float g_x1[BB*EE*F1];
static __device__ float g_h2[BB*EE*DD2];
static __device__ float g_s2[BB*EE];
static __device__ float g_d2[BB*EE];
static __device__ float g_alpha2[BB*EE*EE];
static __device__ float g_o2[BB*EE*DD2];
static __device__ float g_x2[BB*EE*DD2];
static __device__ float g_p[BB*EE*512];      // [row][512] = [p1|p2]
static __device__ float g_cls[BB*256];
static __device__ float g_rel[NRR*256];
// packed bf16 hi/lo weights (pairs along K)
static __device__ uint32_t g_W1H[(HH/2)*F1], g_W1L[(HH/2)*F1];      // 384x256
static __device__ uint32_t g_W2H[(F1/2)*DD2], g_W2L[(F1/2)*DD2];    // 128x64
static __device__ uint32_t g_WpH[(DD2/2)*512], g_WpL[(DD2/2)*512];  // 32x512

// ---------------- bf16 split helpers ----------------
__device__ __forceinline__ void split2(float v0, float v1, uint32_t& h, uint32_t& l) {
    uint32_t hp, lp;
    asm("cvt.rn.bf16x2.f32 %0, %1, %2;" : "=r"(hp) : "f"(v1), "f"(v0));
    float h0 = __uint_as_float(hp << 16);
    float h1 = __uint_as_float(hp & 0xffff0000u);
    asm("cvt.rn.bf16x2.f32 %0, %1, %2;" : "=r"(lp) : "f"(v1 - h1), "f"(v0 - h0));
    h = hp; l = lp;
}
__device__ __forceinline__ void mma16(float* d, const uint32_t* a, const uint32_t* b) {
    asm volatile(
        "mma.sync.aligned.m16n8k16.row.col.f32.bf16.bf16.f32 "
        "{%0,%1,%2,%3},{%4,%5,%6,%7},{%8,%9},{%0,%1,%2,%3};"
        : "+f"(d[0]), "+f"(d[1]), "+f"(d[2]), "+f"(d[3])
        : "r"(a[0]), "r"(a[1]), "r"(a[2]), "r"(a[3]), "r"(b[0]), "r"(b[1]));
}

// ---------------- 0. weight pre-split ----------------
// W1 pairs: 98304 ; W2 pairs: 8192 ; Wp pairs: 16384 ; total 122880
__global__ void prep_kernel(const float* __restrict__ W1,
                            const float* __restrict__ W2,
                            const float* __restrict__ Wr1) {
    int idx = blockIdx.x * blockDim.x + threadIdx.x;
    if (idx < 98304) {
        int kp = idx >> 8, n = idx & 255;
        uint32_t h, l;
        split2(W1[(size_t)(2*kp)*F1 + n], W1[(size_t)(2*kp+1)*F1 + n], h, l);
        g_W1H[idx] = h; g_W1L[idx] = l;
    } else if (idx < 98304 + 8192) {
        int j = idx - 98304;
        int kp = j >> 6, n = j & 63;
        uint32_t h, l;
        split2(W2[(size_t)(2*kp)*DD2 + n], W2[(size_t)(2*kp+1)*DD2 + n], h, l);
        g_W2H[j] = h; g_W2L[j] = l;
    } else if (idx < 122880) {
        int j = idx - 106496;
        int kp = j >> 9, n = j & 511;
        int col = n & 255;
        int base = (n < 256) ? 0 : 64;
        uint32_t h, l;
        split2(Wr1[(size_t)(base + 2*kp)*256 + col],
               Wr1[(size_t)(base + 2*kp + 1)*256 + col], h, l);
        g_WpH[j] = h; g_WpL[j] = l;
    }
}

// ---------------- 1. entity pooling + type embedding ----------------
__global__ void pool_kernel(const float* __restrict__ seq,
                            const int* __restrict__ starts,
                            const int* __restrict__ type_ids,
                            const float* __restrict__ temb,
                            float* __restrict__ x0) {
    int be = blockIdx.x;
    int b = be >> 7;
    int t = threadIdx.x;                 // 256 threads
    __shared__ float toks[WW*HH];
    __shared__ float colsum[HH];
    __shared__ float logits[WW];

    int start = starts[be];
    const float* base = seq + ((size_t)b*SS + start)*HH;
    for (int i = t; i < WW*HH; i += 256) toks[i] = base[i];
    __syncthreads();

    for (int h = t; h < HH; h += 256) {
        float cs = 0.f;
        #pragma unroll
        for (int w = 0; w < WW; w++) cs += toks[w*HH + h];
        colsum[h] = cs;
    }
    __syncthreads();

    int warp = t >> 5, lane = t & 31;
    {
        float acc = 0.f;
        for (int h = lane; h < HH; h += 32) acc += toks[warp*HH + h] * colsum[h];
        #pragma unroll
        for (int off = 16; off > 0; off >>= 1) acc += __shfl_xor_sync(0xffffffffu, acc, off);
        if (lane == 0) logits[warp] = acc * 0.125f;
    }
    __syncthreads();

    float m = logits[0];
    #pragma unroll
    for (int w = 1; w < WW; w++) m = fmaxf(m, logits[w]);
    float ex[WW]; float sum = 0.f;
    #pragma unroll
    for (int w = 0; w < WW; w++) { ex[w] = __expf(logits[w] - m); sum += ex[w]; }
    float inv = 1.f / sum;

    int type = type_ids[be];
    const float* te = temb + (size_t)type*HH;
    for (int h = t; h < HH; h += 256) {
        float p = 0.f;
        #pragma unroll
        for (int w = 0; w < WW; w++) p += ex[w] * toks[w*HH + h];
        x0[(size_t)be*HH + h] = p*inv + te[h];
    }
}

#define SA 20   // A smem stride (u32)
#define SBp 72  // B smem stride (u32)

// ---------------- GEMM with pre-packed B (weights) ----------------
// C[M,N] = A[M,K] @ B[K,N]; BH/BL packed pairs [K/2][N] u32. N == ldc == ldbN.
__global__ __launch_bounds__(256) void bf16_gemm_pb(
        const float* __restrict__ A,
        const uint32_t* __restrict__ BH, const uint32_t* __restrict__ BL,
        float* __restrict__ C, int M, int N, int K, int lda) {
    __shared__ uint32_t AsH[64][SA], AsL[64][SA];
    __shared__ uint32_t BsH[16][SBp], BsL[16][SBp];

    int tid = threadIdx.x;
    int wid = tid >> 5, lane = tid & 31;
    int g = lane >> 2, ti = lane & 3;
    int warp_m = wid >> 2, warp_n = wid & 3;
    int m0 = blockIdx.y * 64, n0 = blockIdx.x * 64;

    float acc[2][2][4] = {};

    for (int kc = 0; kc < K; kc += 32) {
        #pragma unroll
        for (int i = 0; i < 2; i++) {
            int idx = tid + i*256;
            int row = idx >> 3, q = idx & 7;
            float4 av = *(const float4*)(A + (size_t)(m0 + row)*lda + kc + q*4);
            uint32_t h0, l0, h1, l1;
            split2(av.x, av.y, h0, l0);
            split2(av.z, av.w, h1, l1);
            AsH[row][2*q]   = h0; AsH[row][2*q+1] = h1;
            AsL[row][2*q]   = l0; AsL[row][2*q+1] = l1;
        }
        {
            int r = tid >> 4;               // k-pair 0..15
            int n4 = (tid & 15) * 4;
            size_t off = (size_t)(kc/2 + r)*N + n0 + n4;
            *(uint4*)&BsH[r][n4] = *(const uint4*)(BH + off);
            *(uint4*)&BsL[r][n4] = *(const uint4*)(BL + off);
        }
        __syncthreads();

        #pragma unroll
        for (int s = 0; s < 2; s++) {
            int ab = s*8;
            uint32_t aH[2][4], aL[2][4], bH[2][2], bL[2][2];
            #pragma unroll
            for (int mt = 0; mt < 2; mt++) {
                int rm = warp_m*32 + mt*16;
                aH[mt][0] = AsH[rm + g    ][ab + ti    ];
                aH[mt][1] = AsH[rm + g + 8][ab + ti    ];
                aH[mt][2] = AsH[rm + g    ][ab + ti + 4];
                aH[mt][3] = AsH[rm + g + 8][ab + ti + 4];
                aL[mt][0] = AsL[rm + g    ][ab + ti    ];
                aL[mt][1] = AsL[rm + g + 8][ab + ti    ];
                aL[mt][2] = AsL[rm + g    ][ab + ti + 4];
                aL[mt][3] = AsL[rm + g + 8][ab + ti + 4];
            }
            #pragma unroll
            for (int nt = 0; nt < 2; nt++) {
                int cn = warp_n*16 + nt*8;
                bH[nt][0] = BsH[ab + ti    ][cn + g];
                bH[nt][1] = BsH[ab + ti + 4][cn + g];
                bL[nt][0] = BsL[ab + ti    ][cn + g];
                bL[nt][1] = BsL[ab + ti + 4][cn + g];
            }
            #pragma unroll
            for (int mt = 0; mt < 2; mt++)
                #pragma unroll
                for (int nt = 0; nt < 2; nt++) {
                    mma16(acc[mt][nt], aH[mt], bL[nt]);
                    mma16(acc[mt][nt], aL[mt], bH[nt]);
                    mma16(acc[mt][nt], aH[mt], bH[nt]);
                }
        }
        __syncthreads();
    }

    #pragma unroll
    for (int mt = 0; mt < 2; mt++) {
        int rm = m0 + warp_m*32 + mt*16;
        #pragma unroll
        for (int nt = 0; nt < 2; nt++) {
            int cn = n0 + warp_n*16 + nt*8;
            float* c0 = C + (size_t)(rm + g)*N + cn + 2*ti;
            float* c2 = C + (size_t)(rm + g + 8)*N + cn + 2*ti;
            c0[0] = acc[mt][nt][0]; c0[1] = acc[mt][nt][1];
            c2[0] = acc[mt][nt][2]; c2[1] = acc[mt][nt][3];
        }
    }
}

// ---------------- GEMM with online split (batched; for alpha @ h) ----------------
__global__ __launch_bounds__(256) void bf16_gemm(
        const float* __restrict__ A, const float* __restrict__ Bm,
        float* __restrict__ C,
        int M, int N, int K, int lda, int ldb, int ldc,
        int Hh, long strA, long sBb, long sBh, long sCb, long sCh) {
    int bz = blockIdx.z;
    int bb = bz / Hh, hh = bz - bb*Hh;
    A  += (long)bz * strA;
    Bm += (long)bb * sBb + (long)hh * sBh;
    C  += (long)bb * sCb + (long)hh * sCh;

    __shared__ uint32_t AsH[64][SA], AsL[64][SA];
    __shared__ uint32_t BsH[16][SBp], BsL[16][SBp];

    int tid = threadIdx.x;
    int wid = tid >> 5, lane = tid & 31;
    int g = lane >> 2, ti = lane & 3;
    int warp_m = wid >> 2, warp_n = wid & 3;
    int m0 = blockIdx.y * 64, n0 = blockIdx.x * 64;

    float acc[2][2][4] = {};

    for (int kc = 0; kc < K; kc += 32) {
        #pragma unroll
        for (int i = 0; i < 2; i++) {
            int idx = tid + i*256;
            int row = idx >> 3, q = idx & 7;
            float4 av = *(const float4*)(A + (size_t)(m0 + row)*lda + kc + q*4);
            uint32_t h0, l0, h1, l1;
            split2(av.x, av.y, h0, l0);
            split2(av.z, av.w, h1, l1);
            AsH[row][2*q]   = h0; AsH[row][2*q+1] = h1;
            AsL[row][2*q]   = l0; AsL[row][2*q+1] = l1;
        }
        {
            int r = tid >> 4;
            int n4 = (tid & 15) * 4;
            float4 b0v = *(const float4*)(Bm + (size_t)(kc + 2*r)*ldb + n0 + n4);
            float4 b1v = *(const float4*)(Bm + (size_t)(kc + 2*r + 1)*ldb + n0 + n4);
            uint32_t h, l;
            split2(b0v.x, b1v.x, h, l); BsH[r][n4+0] = h; BsL[r][n4+0] = l;
            split2(b0v.y, b1v.y, h, l); BsH[r][n4+1] = h; BsL[r][n4+1] = l;
            split2(b0v.z, b1v.z, h, l); BsH[r][n4+2] = h; BsL[r][n4+2] = l;
            split2(b0v.w, b1v.w, h, l); BsH[r][n4+3] = h; BsL[r][n4+3] = l;
        }
        __syncthreads();

        #pragma unroll
        for (int s = 0; s < 2; s++) {
            int ab = s*8;
            uint32_t aH[2][4], aL[2][4], bH[2][2], bL[2][2];
            #pragma unroll
            for (int mt = 0; mt < 2; mt++) {
                int rm = warp_m*32 + mt*16;
                aH[mt][0] = AsH[rm + g    ][ab + ti    ];
                aH[mt][1] = AsH[rm + g + 8][ab + ti    ];
                aH[mt][2] = AsH[rm + g    ][ab + ti + 4];
                aH[mt][3] = AsH[rm + g + 8][ab + ti + 4];
                aL[mt][0] = AsL[rm + g    ][ab + ti    ];
                aL[mt][1] = AsL[rm + g + 8][ab + ti    ];
                aL[mt][2] = AsL[rm + g    ][ab + ti + 4];
                aL[mt][3] = AsL[rm + g + 8][ab + ti + 4];
            }
            #pragma unroll
            for (int nt = 0; nt < 2; nt++) {
                int cn = warp_n*16 + nt*8;
                bH[nt][0] = BsH[ab + ti    ][cn + g];
                bH[nt][1] = BsH[ab + ti + 4][cn + g];
                bL[nt][0] = BsL[ab + ti    ][cn + g];
                bL[nt][1] = BsL[ab + ti + 4][cn + g];
            }
            #pragma unroll
            for (int mt = 0; mt < 2; mt++)
                #pragma unroll
                for (int nt = 0; nt < 2; nt++) {
                    mma16(acc[mt][nt], aH[mt], bL[nt]);
                    mma16(acc[mt][nt], aL[mt], bH[nt]);
                    mma16(acc[mt][nt], aH[mt], bH[nt]);
                }
        }
        __syncthreads();
    }

    #pragma unroll
    for (int mt = 0; mt < 2; mt++) {
        int rm = m0 + warp_m*32 + mt*16;
        #pragma unroll
        for (int nt = 0; nt < 2; nt++) {
            int cn = n0 + warp_n*16 + nt*8;
            float* c0 = C + (size_t)(rm + g)*ldc + cn + 2*ti;
            float* c2 = C + (size_t)(rm + g + 8)*ldc + cn + 2*ti;
            c0[0] = acc[mt][nt][0]; c0[1] = acc[mt][nt][1];
            c2[0] = acc[mt][nt][2]; c2[1] = acc[mt][nt][3];
        }
    }
}

// ---------------- s/d attention coefficients (wide) ----------------
__global__ void sd_kernel(const float* __restrict__ h,
                          const float* __restrict__ a_src,
                          const float* __restrict__ a_dst,
                          float* __restrict__ s_out, float* __restrict__ d_out,
                          int F, int Hh, int D) {
    int row = blockIdx.x;
    int t = threadIdx.x;
    float v = h[(size_t)row*F + t];
    __shared__ float ss[256], sd2[256];
    ss[t] = v * a_src[t];
    sd2[t] = v * a_dst[t];
    __syncthreads();
    int dd = t % D;
    for (int st = D >> 1; st > 0; st >>= 1) {
        if (dd < st) { ss[t] += ss[t+st]; sd2[t] += sd2[t+st]; }
        __syncthreads();
    }
    if (dd == 0) {
        int head = t / D;
        int b = row >> 7, e = row & 127;
        int o = (b*Hh + head)*EE + e;
        s_out[o] = ss[t];
        d_out[o] = sd2[t];
    }
}

// ---------------- attention softmax rows (alpha, wide) ----------------
__global__ void alpha_kernel(const float* __restrict__ s,
                             const float* __restrict__ d,
                             float* __restrict__ alpha) {
    int g = (blockIdx.x * blockDim.x + threadIdx.x) >> 5;
    int lane = threadIdx.x & 31;
    int bh = g / EE, i = g % EE;
    float di = d[bh*EE + i];
    float ev[4]; float m = -1e30f;
    #pragma unroll
    for (int q = 0; q < 4; q++) {
        int j = lane + q*32;
        float e = di + s[bh*EE + j];
        e = (e >= 0.f) ? e : 0.2f*e;
        ev[q] = e;
        m = fmaxf(m, e);
    }
    #pragma unroll
    for (int off = 16; off > 0; off >>= 1) m = fmaxf(m, __shfl_xor_sync(0xffffffffu, m, off));
    float sum = 0.f;
    #pragma unroll
    for (int q = 0; q < 4; q++) { ev[q] = __expf(ev[q] - m); sum += ev[q]; }
    #pragma unroll
    for (int off = 16; off > 0; off >>= 1) sum += __shfl_xor_sync(0xffffffffu, sum, off);
    float inv = 1.f / sum;
    #pragma unroll
    for (int q = 0; q < 4; q++)
        alpha[(size_t)(bh*EE + i)*EE + lane + q*32] = ev[q]*inv;
}

// ---------------- bias + layernorm + elu ----------------
__global__ void lnelu_kernel(const float* __restrict__ in,
                             const float* __restrict__ bias,
                             const float* __restrict__ g,
                             const float* __restrict__ bt,
                             float* __restrict__ out, int F) {
    int row = blockIdx.x;
    int t = threadIdx.x;
    float v = in[(size_t)row*F + t] + bias[t];
    float s = v, s2 = v*v;
    #pragma unroll
    for (int off = 16; off > 0; off >>= 1) {
        s  += __shfl_xor_sync(0xffffffffu, s,  off);
        s2 += __shfl_xor_sync(0xffffffffu, s2, off);
    }
    __shared__ float ws[8], ws2[8];
    int wid = t >> 5, lane = t & 31, nw = F >> 5;
    if (lane == 0) { ws[wid] = s; ws2[wid] = s2; }
    __syncthreads();
    float S = 0.f, S2 = 0.f;
    for (int k = 0; k < nw; k++) { S += ws[k]; S2 += ws2[k]; }
    float mean = S / F;
    float var = S2 / F - mean*mean;
    float y = (v - mean) * rsqrtf(var + 1e-5f) * g[t] + bt[t];
    out[(size_t)row*F + t] = (y > 0.f) ? y : expm1f(y);
}

// ---------------- misc: cls projection (+br1) and rel-type projection ----------------
__global__ void misc_kernel(const float* __restrict__ seq,
                            const float* __restrict__ remb,
                            const float* __restrict__ Wr1,
                            const float* __restrict__ br1,
                            float* __restrict__ clsp,
                            float* __restrict__ relp) {
    int blk = blockIdx.x;
    int c = threadIdx.x;  // 256
    if (blk < BB) {
        int b = blk;
        __shared__ float cls[HH];
        for (int h = c; h < HH; h += 256) cls[h] = seq[(size_t)b*SS*HH + h];
        __syncthreads();
        float acc = br1[c];
        const float* w = Wr1 + (size_t)160*256 + c;
        for (int h = 0; h < HH; h++) acc += cls[h] * w[(size_t)h*256];
        clsp[b*256 + c] = acc;
    } else {
        int r = blk - BB;
        __shared__ float rv[RDD];
        if (c < RDD) rv[c] = remb[r*RDD + c];
        __syncthreads();
        float acc = 0.f;
        #pragma unroll
        for (int k = 0; k < RDD; k++) acc += rv[k] * Wr1[(size_t)(128 + k)*256 + c];
        relp[r*256 + c] = acc;
    }
}

// ---------------- final pair scores ----------------
__global__ void pair_kernel(const int* __restrict__ pidx,
                            const int* __restrict__ rids,
                            const float* __restrict__ p,
                            const float* __restrict__ relp,
                            const float* __restrict__ clsp,
                            const float* __restrict__ Wr2,
                            const float* __restrict__ br2,
                            float* __restrict__ out) {
    int g = (blockIdx.x * blockDim.x + threadIdx.x) >> 5;
    int lane = threadIdx.x & 31;
    int b = g / PP, pidx_p = g % PP;
    int pi = pidx[(b*PP + pidx_p)*2 + 0];
    int pj = pidx[(b*PP + pidx_p)*2 + 1];
    int r  = rids[b*PP + pidx_p];
    const float* a1 = p + (size_t)(b*EE + pi)*512;
    const float* a2 = p + (size_t)(b*EE + pj)*512 + 256;
    const float* ar = relp + r*256;
    const float* ac = clsp + b*256;
    float acc = 0.f;
    #pragma unroll
    for (int q = 0; q < 8; q++) {
        int c = lane + q*32;
        float v = a1[c] + a2[c] + ar[c] + ac[c];
        v = fmaxf(v, 0.f);
        acc += v * Wr2[c];
    }
    #pragma unroll
    for (int off = 16; off > 0; off >>= 1) acc += __shfl_xor_sync(0xffffffffu, acc, off);
    if (lane == 0) out[b*PP + pidx_p] = acc + br2[0];
}

// ---------------- launch ----------------
extern "C" void kernel_launch(void* const* d_in, const int* in_sizes, int n_in,
                              void* d_out, int out_size) {
    const float* seq      = (const float*)d_in[0];
    const int*   starts   = (const int*)  d_in[1];
    const int*   type_ids = (const int*)  d_in[2];
    const int*   pair_idx = (const int*)  d_in[3];
    const int*   rel_ids  = (const int*)  d_in[4];
    const float* temb     = (const float*)d_in[5];
    const float* remb     = (const float*)d_in[6];
    const float* W1       = (const float*)d_in[7];
    const float* a_src1   = (const float*)d_in[8];
    const float* a_dst1   = (const float*)d_in[9];
    const float* b1       = (const float*)d_in[10];
    const float* ln1_g    = (const float*)d_in[11];
    const float* ln1_b    = (const float*)d_in[12];
    const float* W2       = (const float*)d_in[13];
    const float* a_src2   = (const float*)d_in[14];
    const float* a_dst2   = (const float*)d_in[15];
    const float* b2       = (const float*)d_in[16];
    const float* ln2_g    = (const float*)d_in[17];
    const float* ln2_b    = (const float*)d_in[18];
    const float* Wr1      = (const float*)d_in[19];
    const float* br1      = (const float*)d_in[20];
    const float* Wr2      = (const float*)d_in[21];
    const float* br2      = (const float*)d_in[22];
    float* out = (float*)d_out;

    float *x0, *h1, *s1, *d1, *al1, *o1, *x1, *h2, *s2, *d2, *al2, *o2, *x2;
    float *p, *clsp, *relp;
    uint32_t *W1H, *W1L, *W2H, *W2L, *WpH, *WpL;
    cudaGetSymbolAddress((void**)&x0,  g_x0);
    cudaGetSymbolAddress((void**)&h1,  g_h1);
    cudaGetSymbolAddress((void**)&s1,  g_s1);
    cudaGetSymbolAddress((void**)&d1,  g_d1);
    cudaGetSymbolAddress((void**)&al1, g_alpha1);
    cudaGetSymbolAddress((void**)&o1,  g_o1);
    cudaGetSymbolAddress((void**)&x1,  g_x1);
    cudaGetSymbolAddress((void**)&h2,  g_h2);
    cudaGetSymbolAddress((void**)&s2,  g_s2);
    cudaGetSymbolAddress((void**)&d2,  g_d2);
    cudaGetSymbolAddress((void**)&al2, g_alpha2);
    cudaGetSymbolAddress((void**)&o2,  g_o2);
    cudaGetSymbolAddress((void**)&x2,  g_x2);
    cudaGetSymbolAddress((void**)&p,   g_p);
    cudaGetSymbolAddress((void**)&clsp, g_cls);
    cudaGetSymbolAddress((void**)&relp, g_rel);
    cudaGetSymbolAddress((void**)&W1H, g_W1H);
    cudaGetSymbolAddress((void**)&W1L, g_W1L);
    cudaGetSymbolAddress((void**)&W2H, g_W2H);
    cudaGetSymbolAddress((void**)&W2L, g_W2L);
    cudaGetSymbolAddress((void**)&WpH, g_WpH);
    cudaGetSymbolAddress((void**)&WpL, g_WpL);

    // 0. pre-split weights (independent of pooling)
    prep_kernel<<<240, 512>>>(W1, W2, Wr1);

    // 1. pooling + type emb
    pool_kernel<<<BB*EE, 256>>>(seq, starts, type_ids, temb, x0);

    // 2. h1 = x0 @ W1  (4096,768)@(768,256)
    bf16_gemm_pb<<<dim3(4, 64), 256>>>(x0, W1H, W1L, h1, BB*EE, F1, HH, HH);

    // 3. s1,d1
    sd_kernel<<<BB*EE, F1>>>(h1, a_src1, a_dst1, s1, d1, F1, HEADS1, DD1);

    // 4. alpha1
    alpha_kernel<<<(BB*HEADS1*EE)/4, 128>>>(s1, d1, al1);

    // 5. o1 = alpha1 @ h1 per (b,head)
    bf16_gemm<<<dim3(2, 2, BB*HEADS1), 256>>>(al1, h1, o1, EE, DD1, EE,
                                              EE, F1, F1, HEADS1,
                                              (long)EE*EE, (long)EE*F1, DD1,
                                              (long)EE*F1, DD1);

    // 6. x1 = elu(ln(o1 + b1))
    lnelu_kernel<<<BB*EE, F1>>>(o1, b1, ln1_g, ln1_b, x1, F1);

    // 7. h2 = x1 @ W2  (4096,256)@(256,64)
    bf16_gemm_pb<<<dim3(1, 64), 256>>>(x1, W2H, W2L, h2, BB*EE, DD2, F1, F1);

    // 8. s2,d2
    sd_kernel<<<BB*EE, DD2>>>(h2, a_src2, a_dst2, s2, d2, DD2, 1, DD2);

    // 9. alpha2
    alpha_kernel<<<(BB*EE)/4, 128>>>(s2, d2, al2);

    // 10. o2 = alpha2 @ h2 per b
    bf16_gemm<<<dim3(1, 2, BB), 256>>>(al2, h2, o2, EE, DD2, EE,
                                       EE, DD2, DD2, 1,
                                       (long)EE*EE, (long)EE*DD2, 0,
                                       (long)EE*DD2, 0);

    // 11. x2 = elu(ln(o2 + b2))
    lnelu_kernel<<<BB*EE, DD2>>>(o2, b2, ln2_g, ln2_b, x2, DD2);

    // 12. pair projections: single GEMM (4096,64)@(64,512) -> p=[p1|p2]
    bf16_gemm_pb<<<dim3(8, 64), 256>>>(x2, WpH, WpL, p, BB*EE, 512, DD2, DD2);

    // 13. cls (+br1) and rel projections
    misc_kernel<<<BB + NRR, 256>>>(seq, remb, Wr1, br1, clsp, relp);

    // 14. pair scores
    pair_kernel<<<(BB*PP)/8, 256>>>(pair_idx, rel_ids, p, relp, clsp,
                                    Wr2, br2, out);
}

// round 5
// speedup vs baseline: 1.4839x; 1.1193x over previous
#include <cuda_runtime.h>
#include <cuda_bf16.h>
#include <math.h>
#include <stdint.h>

#define BB 32
#define SS 1024
#define HH 768
#define EE 128
#define WW 8
#define PP 512
#define NTT 5
#define NRR 9
#define DD1 128
#define HEADS1 2
#define DD2 64
#define RDD 32
#define F1 256  // HEADS1*DD1

// ---------------- scratch ----------------
static __device__ float g_x0[BB*EE*HH];
static __device__ float g_h1[BB*EE*F1];
static __device__ float g_s1[BB*HEADS1*EE];
static __device__ float g_d1[BB*HEADS1*EE];
static __device__ float g_o1[BB*EE*F1];
static __device__ float g_x1[BB*EE*F1];
static __device__ float g_h2[BB*EE*DD2];
static __device__ float g_s2[BB*EE];
static __device__ float g_d2[BB*EE];
static __device__ float g_o2[BB*EE*DD2];
static __device__ float g_x2[BB*EE*DD2];
static __device__ float g_p[BB*EE*512];      // [row][512] = [p1|p2]
static __device__ float g_cls[BB*256];
static __device__ float g_rel[NRR*256];
// packed bf16 hi/lo weights (pairs along K)
static __device__ uint32_t g_W1H[(HH/2)*F1], g_W1L[(HH/2)*F1];      // 384x256
static __device__ uint32_t g_W2H[(F1/2)*DD2], g_W2L[(F1/2)*DD2];    // 128x64
static __device__ uint32_t g_WpH[(DD2/2)*512], g_WpL[(DD2/2)*512];  // 32x512

// ---------------- bf16 split helpers ----------------
__device__ __forceinline__ void split2(float v0, float v1, uint32_t& h, uint32_t& l) {
    uint32_t hp, lp;
    asm("cvt.rn.bf16x2.f32 %0, %1, %2;" : "=r"(hp) : "f"(v1), "f"(v0));
    float h0 = __uint_as_float(hp << 16);
    float h1 = __uint_as_float(hp & 0xffff0000u);
    asm("cvt.rn.bf16x2.f32 %0, %1, %2;" : "=r"(lp) : "f"(v1 - h1), "f"(v0 - h0));
    h = hp; l = lp;
}
__device__ __forceinline__ void mma16(float* d, const uint32_t* a, const uint32_t* b) {
    asm volatile(
        "mma.sync.aligned.m16n8k16.row.col.f32.bf16.bf16.f32 "
        "{%0,%1,%2,%3},{%4,%5,%6,%7},{%8,%9},{%0,%1,%2,%3};"
        : "+f"(d[0]), "+f"(d[1]), "+f"(d[2]), "+f"(d[3])
        : "r"(a[0]), "r"(a[1]), "r"(a[2]), "r"(a[3]), "r"(b[0]), "r"(b[1]));
}

// ---------------- 0. weight pre-split ----------------
__global__ void prep_kernel(const float* __restrict__ W1,
                            const float* __restrict__ W2,
                            const float* __restrict__ Wr1) {
    int idx = blockIdx.x * blockDim.x + threadIdx.x;
    if (idx < 98304) {
        int kp = idx >> 8, n = idx & 255;
        uint32_t h, l;
        split2(W1[(size_t)(2*kp)*F1 + n], W1[(size_t)(2*kp+1)*F1 + n], h, l);
        g_W1H[idx] = h; g_W1L[idx] = l;
    } else if (idx < 98304 + 8192) {
        int j = idx - 98304;
        int kp = j >> 6, n = j & 63;
        uint32_t h, l;
        split2(W2[(size_t)(2*kp)*DD2 + n], W2[(size_t)(2*kp+1)*DD2 + n], h, l);
        g_W2H[j] = h; g_W2L[j] = l;
    } else if (idx < 122880) {
        int j = idx - 106496;
        int kp = j >> 9, n = j & 511;
        int col = n & 255;
        int base = (n < 256) ? 0 : 64;
        uint32_t h, l;
        split2(Wr1[(size_t)(base + 2*kp)*256 + col],
               Wr1[(size_t)(base + 2*kp + 1)*256 + col], h, l);
        g_WpH[j] = h; g_WpL[j] = l;
    }
}

// ---------------- 1. entity pooling + type embedding (float4) ----------------
__global__ void pool_kernel(const float* __restrict__ seq,
                            const int* __restrict__ starts,
                            const int* __restrict__ type_ids,
                            const float* __restrict__ temb,
                            float* __restrict__ x0) {
    int be = blockIdx.x;
    int b = be >> 7;
    int t = threadIdx.x;                 // 256 threads
    __shared__ float4 toks4[WW*HH/4];    // 24 KB
    float* toks = (float*)toks4;
    __shared__ float colsum[HH];
    __shared__ float logits[WW];

    int start = starts[be];
    const float4* base4 = (const float4*)(seq + ((size_t)b*SS + start)*HH);
    #pragma unroll
    for (int i = 0; i < 6; i++) toks4[t + i*256] = base4[t + i*256];
    __syncthreads();

    for (int h = t; h < HH; h += 256) {
        float cs = 0.f;
        #pragma unroll
        for (int w = 0; w < WW; w++) cs += toks[w*HH + h];
        colsum[h] = cs;
    }
    __syncthreads();

    int warp = t >> 5, lane = t & 31;
    {
        float acc = 0.f;
        for (int h = lane; h < HH; h += 32) acc += toks[warp*HH + h] * colsum[h];
        #pragma unroll
        for (int off = 16; off > 0; off >>= 1) acc += __shfl_xor_sync(0xffffffffu, acc, off);
        if (lane == 0) logits[warp] = acc * 0.125f;
    }
    __syncthreads();

    float m = logits[0];
    #pragma unroll
    for (int w = 1; w < WW; w++) m = fmaxf(m, logits[w]);
    float ex[WW]; float sum = 0.f;
    #pragma unroll
    for (int w = 0; w < WW; w++) { ex[w] = __expf(logits[w] - m); sum += ex[w]; }
    float inv = 1.f / sum;

    int type = type_ids[be];
    const float* te = temb + (size_t)type*HH;
    for (int h = t; h < HH; h += 256) {
        float p = 0.f;
        #pragma unroll
        for (int w = 0; w < WW; w++) p += ex[w] * toks[w*HH + h];
        x0[(size_t)be*HH + h] = p*inv + te[h];
    }
}

#define SA 20   // A smem stride (u32)
#define SBp 72  // B smem stride (u32)

// ---------------- GEMM with pre-packed B (weights) ----------------
__global__ __launch_bounds__(256) void bf16_gemm_pb(
        const float* __restrict__ A,
        const uint32_t* __restrict__ BH, const uint32_t* __restrict__ BL,
        float* __restrict__ C, int M, int N, int K, int lda) {
    __shared__ uint32_t AsH[64][SA], AsL[64][SA];
    __shared__ uint32_t BsH[16][SBp], BsL[16][SBp];

    int tid = threadIdx.x;
    int wid = tid >> 5, lane = tid & 31;
    int g = lane >> 2, ti = lane & 3;
    int warp_m = wid >> 2, warp_n = wid & 3;
    int m0 = blockIdx.y * 64, n0 = blockIdx.x * 64;

    float acc[2][2][4] = {};

    for (int kc = 0; kc < K; kc += 32) {
        #pragma unroll
        for (int i = 0; i < 2; i++) {
            int idx = tid + i*256;
            int row = idx >> 3, q = idx & 7;
            float4 av = *(const float4*)(A + (size_t)(m0 + row)*lda + kc + q*4);
            uint32_t h0, l0, h1, l1;
            split2(av.x, av.y, h0, l0);
            split2(av.z, av.w, h1, l1);
            AsH[row][2*q]   = h0; AsH[row][2*q+1] = h1;
            AsL[row][2*q]   = l0; AsL[row][2*q+1] = l1;
        }
        {
            int r = tid >> 4;
            int n4 = (tid & 15) * 4;
            size_t off = (size_t)(kc/2 + r)*N + n0 + n4;
            *(uint4*)&BsH[r][n4] = *(const uint4*)(BH + off);
            *(uint4*)&BsL[r][n4] = *(const uint4*)(BL + off);
        }
        __syncthreads();

        #pragma unroll
        for (int s = 0; s < 2; s++) {
            int ab = s*8;
            uint32_t aH[2][4], aL[2][4], bH[2][2], bL[2][2];
            #pragma unroll
            for (int mt = 0; mt < 2; mt++) {
                int rm = warp_m*32 + mt*16;
                aH[mt][0] = AsH[rm + g    ][ab + ti    ];
                aH[mt][1] = AsH[rm + g + 8][ab + ti    ];
                aH[mt][2] = AsH[rm + g    ][ab + ti + 4];
                aH[mt][3] = AsH[rm + g + 8][ab + ti + 4];
                aL[mt][0] = AsL[rm + g    ][ab + ti    ];
                aL[mt][1] = AsL[rm + g + 8][ab + ti    ];
                aL[mt][2] = AsL[rm + g    ][ab + ti + 4];
                aL[mt][3] = AsL[rm + g + 8][ab + ti + 4];
            }
            #pragma unroll
            for (int nt = 0; nt < 2; nt++) {
                int cn = warp_n*16 + nt*8;
                bH[nt][0] = BsH[ab + ti    ][cn + g];
                bH[nt][1] = BsH[ab + ti + 4][cn + g];
                bL[nt][0] = BsL[ab + ti    ][cn + g];
                bL[nt][1] = BsL[ab + ti + 4][cn + g];
            }
            #pragma unroll
            for (int mt = 0; mt < 2; mt++)
                #pragma unroll
                for (int nt = 0; nt < 2; nt++) {
                    mma16(acc[mt][nt], aH[mt], bL[nt]);
                    mma16(acc[mt][nt], aL[mt], bH[nt]);
                    mma16(acc[mt][nt], aH[mt], bH[nt]);
                }
        }
        __syncthreads();
    }

    #pragma unroll
    for (int mt = 0; mt < 2; mt++) {
        int rm = m0 + warp_m*32 + mt*16;
        #pragma unroll
        for (int nt = 0; nt < 2; nt++) {
            int cn = n0 + warp_n*16 + nt*8;
            float* c0 = C + (size_t)(rm + g)*N + cn + 2*ti;
            float* c2 = C + (size_t)(rm + g + 8)*N + cn + 2*ti;
            c0[0] = acc[mt][nt][0]; c0[1] = acc[mt][nt][1];
            c2[0] = acc[mt][nt][2]; c2[1] = acc[mt][nt][3];
        }
    }
}

// ---------------- attention GEMM: C = softmax_rows(leaky(d_i+s_j)) @ B ----------------
// K = EE = 128 fixed. Alpha materialized in-register from s,d (no global alpha).
// Batched over z; s,d indexed [z*EE + .]; B offset bb*sBb + hh*sBh.
__global__ __launch_bounds__(256) void attn_gemm(
        const float* __restrict__ s_in, const float* __restrict__ d_in,
        const float* __restrict__ Bm, float* __restrict__ C,
        int N, int ldb, int ldc,
        int Hh, long sBb, long sBh, long sCb, long sCh) {
    int bz = blockIdx.z;
    int bb = bz / Hh, hh = bz - bb*Hh;
    const float* sp = s_in + (size_t)bz*EE;
    const float* dp = d_in + (size_t)bz*EE;
    Bm += (long)bb * sBb + (long)hh * sBh;
    C  += (long)bb * sCb + (long)hh * sCh;

    __shared__ uint32_t AsH[64][SA], AsL[64][SA];
    __shared__ uint32_t BsH[16][SBp], BsL[16][SBp];
    __shared__ float s_sh[EE], d_sh[64], m_sh[64], inv_sh[64];

    int tid = threadIdx.x;
    int wid = tid >> 5, lane = tid & 31;
    int g = lane >> 2, ti = lane & 3;
    int warp_m = wid >> 2, warp_n = wid & 3;
    int m0 = blockIdx.y * 64, n0 = blockIdx.x * 64;

    if (tid < EE) s_sh[tid] = sp[tid];
    else if (tid < EE + 64) d_sh[tid - EE] = dp[m0 + tid - EE];
    __syncthreads();

    // per-row softmax stats: warp w handles rows w*8..w*8+7
    #pragma unroll
    for (int rr = 0; rr < 8; rr++) {
        int i = wid*8 + rr;
        float di = d_sh[i];
        float ev[4]; float m = -1e30f;
        #pragma unroll
        for (int q = 0; q < 4; q++) {
            float e = di + s_sh[lane + q*32];
            e = fmaxf(e, 0.2f*e);
            ev[q] = e;
            m = fmaxf(m, e);
        }
        #pragma unroll
        for (int off = 16; off > 0; off >>= 1) m = fmaxf(m, __shfl_xor_sync(0xffffffffu, m, off));
        float sum = 0.f;
        #pragma unroll
        for (int q = 0; q < 4; q++) sum += __expf(ev[q] - m);
        #pragma unroll
        for (int off = 16; off > 0; off >>= 1) sum += __shfl_xor_sync(0xffffffffu, sum, off);
        if (lane == 0) { m_sh[i] = m; inv_sh[i] = 1.f / sum; }
    }
    __syncthreads();

    float acc[2][2][4] = {};

    for (int kc = 0; kc < EE; kc += 32) {
        // A tile = alpha values computed on the fly
        #pragma unroll
        for (int i = 0; i < 2; i++) {
            int idx = tid + i*256;
            int row = idx >> 3, q = idx & 7;
            float di = d_sh[row], mi = m_sh[row], ii = inv_sh[row];
            float v[4];
            #pragma unroll
            for (int tq = 0; tq < 4; tq++) {
                float e = di + s_sh[kc + 4*q + tq];
                e = fmaxf(e, 0.2f*e);
                v[tq] = __expf(e - mi) * ii;
            }
            uint32_t h0, l0, h1, l1;
            split2(v[0], v[1], h0, l0);
            split2(v[2], v[3], h1, l1);
            AsH[row][2*q]   = h0; AsH[row][2*q+1] = h1;
            AsL[row][2*q]   = l0; AsL[row][2*q+1] = l1;
        }
        // B tile: online split
        {
            int r = tid >> 4;
            int n4 = (tid & 15) * 4;
            float4 b0v = *(const float4*)(Bm + (size_t)(kc + 2*r)*ldb + n0 + n4);
            float4 b1v = *(const float4*)(Bm + (size_t)(kc + 2*r + 1)*ldb + n0 + n4);
            uint32_t h, l;
            split2(b0v.x, b1v.x, h, l); BsH[r][n4+0] = h; BsL[r][n4+0] = l;
            split2(b0v.y, b1v.y, h, l); BsH[r][n4+1] = h; BsL[r][n4+1] = l;
            split2(b0v.z, b1v.z, h, l); BsH[r][n4+2] = h; BsL[r][n4+2] = l;
            split2(b0v.w, b1v.w, h, l); BsH[r][n4+3] = h; BsL[r][n4+3] = l;
        }
        __syncthreads();

        #pragma unroll
        for (int s = 0; s < 2; s++) {
            int ab = s*8;
            uint32_t aH[2][4], aL[2][4], bH[2][2], bL[2][2];
            #pragma unroll
            for (int mt = 0; mt < 2; mt++) {
                int rm = warp_m*32 + mt*16;
                aH[mt][0] = AsH[rm + g    ][ab + ti    ];
                aH[mt][1] = AsH[rm + g + 8][ab + ti    ];
                aH[mt][2] = AsH[rm + g    ][ab + ti + 4];
                aH[mt][3] = AsH[rm + g + 8][ab + ti + 4];
                aL[mt][0] = AsL[rm + g    ][ab + ti    ];
                aL[mt][1] = AsL[rm + g + 8][ab + ti    ];
                aL[mt][2] = AsL[rm + g    ][ab + ti + 4];
                aL[mt][3] = AsL[rm + g + 8][ab + ti + 4];
            }
            #pragma unroll
            for (int nt = 0; nt < 2; nt++) {
                int cn = warp_n*16 + nt*8;
                bH[nt][0] = BsH[ab + ti    ][cn + g];
                bH[nt][1] = BsH[ab + ti + 4][cn + g];
                bL[nt][0] = BsL[ab + ti    ][cn + g];
                bL[nt][1] = BsL[ab + ti + 4][cn + g];
            }
            #pragma unroll
            for (int mt = 0; mt < 2; mt++)
                #pragma unroll
                for (int nt = 0; nt < 2; nt++) {
                    mma16(acc[mt][nt], aH[mt], bL[nt]);
                    mma16(acc[mt][nt], aL[mt], bH[nt]);
                    mma16(acc[mt][nt], aH[mt], bH[nt]);
                }
        }
        __syncthreads();
    }

    #pragma unroll
    for (int mt = 0; mt < 2; mt++) {
        int rm = m0 + warp_m*32 + mt*16;
        #pragma unroll
        for (int nt = 0; nt < 2; nt++) {
            int cn = n0 + warp_n*16 + nt*8;
            float* c0 = C + (size_t)(rm + g)*ldc + cn + 2*ti;
            float* c2 = C + (size_t)(rm + g + 8)*ldc + cn + 2*ti;
            c0[0] = acc[mt][nt][0]; c0[1] = acc[mt][nt][1];
            c2[0] = acc[mt][nt][2]; c2[1] = acc[mt][nt][3];
        }
    }
}

// ---------------- s/d coefficients, warp-per-row ----------------
__global__ void sd256_kernel(const float* __restrict__ h,
                             const float* __restrict__ a_src,
                             const float* __restrict__ a_dst,
                             float* __restrict__ s_out, float* __restrict__ d_out) {
    __shared__ float as_sh[256], ad_sh[256];
    int t = threadIdx.x;
    as_sh[t] = a_src[t]; ad_sh[t] = a_dst[t];
    __syncthreads();
    int row = blockIdx.x*8 + (t >> 5);
    int lane = t & 31;
    const float* hr = h + (size_t)row*256;
    float4 v0 = *(const float4*)(hr + 4*lane);
    float4 v1 = *(const float4*)(hr + 128 + 4*lane);
    int c0 = 4*lane, c1 = 128 + 4*lane;
    float s0 = v0.x*as_sh[c0] + v0.y*as_sh[c0+1] + v0.z*as_sh[c0+2] + v0.w*as_sh[c0+3];
    float d0 = v0.x*ad_sh[c0] + v0.y*ad_sh[c0+1] + v0.z*ad_sh[c0+2] + v0.w*ad_sh[c0+3];
    float s1v = v1.x*as_sh[c1] + v1.y*as_sh[c1+1] + v1.z*as_sh[c1+2] + v1.w*as_sh[c1+3];
    float d1v = v1.x*ad_sh[c1] + v1.y*ad_sh[c1+1] + v1.z*ad_sh[c1+2] + v1.w*ad_sh[c1+3];
    #pragma unroll
    for (int off = 16; off > 0; off >>= 1) {
        s0  += __shfl_xor_sync(0xffffffffu, s0,  off);
        d0  += __shfl_xor_sync(0xffffffffu, d0,  off);
        s1v += __shfl_xor_sync(0xffffffffu, s1v, off);
        d1v += __shfl_xor_sync(0xffffffffu, d1v, off);
    }
    if (lane == 0) {
        int b = row >> 7, e = row & 127;
        s_out[(b*2+0)*EE + e] = s0;
        d_out[(b*2+0)*EE + e] = d0;
        s_out[(b*2+1)*EE + e] = s1v;
        d_out[(b*2+1)*EE + e] = d1v;
    }
}

__global__ void sd64_kernel(const float* __restrict__ h,
                            const float* __restrict__ a_src,
                            const float* __restrict__ a_dst,
                            float* __restrict__ s_out, float* __restrict__ d_out) {
    int t = threadIdx.x;
    int row = blockIdx.x*8 + (t >> 5);
    int lane = t & 31;
    const float* hr = h + (size_t)row*64;
    float2 v = *(const float2*)(hr + 2*lane);
    float s = v.x*a_src[2*lane] + v.y*a_src[2*lane+1];
    float d = v.x*a_dst[2*lane] + v.y*a_dst[2*lane+1];
    #pragma unroll
    for (int off = 16; off > 0; off >>= 1) {
        s += __shfl_xor_sync(0xffffffffu, s, off);
        d += __shfl_xor_sync(0xffffffffu, d, off);
    }
    if (lane == 0) { s_out[row] = s; d_out[row] = d; }
}

// ---------------- bias + layernorm + elu, warp-per-row ----------------
__global__ void ln256_kernel(const float* __restrict__ in,
                             const float* __restrict__ bias,
                             const float* __restrict__ g,
                             const float* __restrict__ bt,
                             float* __restrict__ out) {
    int t = threadIdx.x;
    int row = blockIdx.x*8 + (t >> 5);
    int lane = t & 31;
    int c0 = 4*lane, c1 = 128 + 4*lane;
    const float* ir = in + (size_t)row*256;
    float4 v0 = *(const float4*)(ir + c0);
    float4 v1 = *(const float4*)(ir + c1);
    float4 b0 = *(const float4*)(bias + c0);
    float4 b1 = *(const float4*)(bias + c1);
    v0.x += b0.x; v0.y += b0.y; v0.z += b0.z; v0.w += b0.w;
    v1.x += b1.x; v1.y += b1.y; v1.z += b1.z; v1.w += b1.w;
    float s  = v0.x+v0.y+v0.z+v0.w + v1.x+v1.y+v1.z+v1.w;
    float s2 = v0.x*v0.x+v0.y*v0.y+v0.z*v0.z+v0.w*v0.w
             + v1.x*v1.x+v1.y*v1.y+v1.z*v1.z+v1.w*v1.w;
    #pragma unroll
    for (int off = 16; off > 0; off >>= 1) {
        s  += __shfl_xor_sync(0xffffffffu, s,  off);
        s2 += __shfl_xor_sync(0xffffffffu, s2, off);
    }
    float mean = s * (1.f/256.f);
    float var  = s2 * (1.f/256.f) - mean*mean;
    float r = rsqrtf(var + 1e-5f);
    float4 g0 = *(const float4*)(g + c0);
    float4 g1 = *(const float4*)(g + c1);
    float4 t0 = *(const float4*)(bt + c0);
    float4 t1 = *(const float4*)(bt + c1);
    float4 o0, o1;
    o0.x = (v0.x-mean)*r*g0.x + t0.x; o0.y = (v0.y-mean)*r*g0.y + t0.y;
    o0.z = (v0.z-mean)*r*g0.z + t0.z; o0.w = (v0.w-mean)*r*g0.w + t0.w;
    o1.x = (v1.x-mean)*r*g1.x + t1.x; o1.y = (v1.y-mean)*r*g1.y + t1.y;
    o1.z = (v1.z-mean)*r*g1.z + t1.z; o1.w = (v1.w-mean)*r*g1.w + t1.w;
    o0.x = o0.x > 0.f ? o0.x : expm1f(o0.x); o0.y = o0.y > 0.f ? o0.y : expm1f(o0.y);
    o0.z = o0.z > 0.f ? o0.z : expm1f(o0.z); o0.w = o0.w > 0.f ? o0.w : expm1f(o0.w);
    o1.x = o1.x > 0.f ? o1.x : expm1f(o1.x); o1.y = o1.y > 0.f ? o1.y : expm1f(o1.y);
    o1.z = o1.z > 0.f ? o1.z : expm1f(o1.z); o1.w = o1.w > 0.f ? o1.w : expm1f(o1.w);
    float* orow = out + (size_t)row*256;
    *(float4*)(orow + c0) = o0;
    *(float4*)(orow + c1) = o1;
}

__global__ void ln64_kernel(const float* __restrict__ in,
                            const float* __restrict__ bias,
                            const float* __restrict__ g,
                            const float* __restrict__ bt,
                            float* __restrict__ out) {
    int t = threadIdx.x;
    int row = blockIdx.x*8 + (t >> 5);
    int lane = t & 31;
    int c = 2*lane;
    const float* ir = in + (size_t)row*64;
    float2 v = *(const float2*)(ir + c);
    float2 b = *(const float2*)(bias + c);
    v.x += b.x; v.y += b.y;
    float s = v.x + v.y, s2 = v.x*v.x + v.y*v.y;
    #pragma unroll
    for (int off = 16; off > 0; off >>= 1) {
        s  += __shfl_xor_sync(0xffffffffu, s,  off);
        s2 += __shfl_xor_sync(0xffffffffu, s2, off);
    }
    float mean = s * (1.f/64.f);
    float var  = s2 * (1.f/64.f) - mean*mean;
    float r = rsqrtf(var + 1e-5f);
    float2 gg = *(const float2*)(g + c);
    float2 tt = *(const float2*)(bt + c);
    float2 o;
    o.x = (v.x-mean)*r*gg.x + tt.x;
    o.y = (v.y-mean)*r*gg.y + tt.y;
    o.x = o.x > 0.f ? o.x : expm1f(o.x);
    o.y = o.y > 0.f ? o.y : expm1f(o.y);
    *(float2*)(out + (size_t)row*64 + c) = o;
}

// ---------------- misc: cls projection (+br1) and rel-type projection ----------------
__global__ void misc_kernel(const float* __restrict__ seq,
                            const float* __restrict__ remb,
                            const float* __restrict__ Wr1,
                            const float* __restrict__ br1,
                            float* __restrict__ clsp,
                            float* __restrict__ relp) {
    int blk = blockIdx.x;
    int c = threadIdx.x;  // 256
    if (blk < BB) {
        int b = blk;
        __shared__ float cls[HH];
        for (int h = c; h < HH; h += 256) cls[h] = seq[(size_t)b*SS*HH + h];
        __syncthreads();
        float acc = br1[c];
        const float* w = Wr1 + (size_t)160*256 + c;
        for (int h = 0; h < HH; h++) acc += cls[h] * w[(size_t)h*256];
        clsp[b*256 + c] = acc;
    } else {
        int r = blk - BB;
        __shared__ float rv[RDD];
        if (c < RDD) rv[c] = remb[r*RDD + c];
        __syncthreads();
        float acc = 0.f;
        #pragma unroll
        for (int k = 0; k < RDD; k++) acc += rv[k] * Wr1[(size_t)(128 + k)*256 + c];
        relp[r*256 + c] = acc;
    }
}

// ---------------- final pair scores ----------------
__global__ void pair_kernel(const int* __restrict__ pidx,
                            const int* __restrict__ rids,
                            const float* __restrict__ p,
                            const float* __restrict__ relp,
                            const float* __restrict__ clsp,
                            const float* __restrict__ Wr2,
                            const float* __restrict__ br2,
                            float* __restrict__ out) {
    int g = (blockIdx.x * blockDim.x + threadIdx.x) >> 5;
    int lane = threadIdx.x & 31;
    int b = g / PP, pp = g % PP;
    int pi = pidx[(b*PP + pp)*2 + 0];
    int pj = pidx[(b*PP + pp)*2 + 1];
    int r  = rids[b*PP + pp];
    const float* a1 = p + (size_t)(b*EE + pi)*512;
    const float* a2 = p + (size_t)(b*EE + pj)*512 + 256;
    const float* ar = relp + r*256;
    const float* ac = clsp + b*256;
    float acc = 0.f;
    #pragma unroll
    for (int q = 0; q < 8; q++) {
        int c = lane + q*32;
        float v = a1[c] + a2[c] + ar[c] + ac[c];
        v = fmaxf(v, 0.f);
        acc += v * Wr2[c];
    }
    #pragma unroll
    for (int off = 16; off > 0; off >>= 1) acc += __shfl_xor_sync(0xffffffffu, acc, off);
    if (lane == 0) out[b*PP + pp] = acc + br2[0];
}

// ---------------- launch ----------------
extern "C" void kernel_launch(void* const* d_in, const int* in_sizes, int n_in,
                              void* d_out, int out_size) {
    const float* seq      = (const float*)d_in[0];
    const int*   starts   = (const int*)  d_in[1];
    const int*   type_ids = (const int*)  d_in[2];
    const int*   pair_idx = (const int*)  d_in[3];
    const int*   rel_ids  = (const int*)  d_in[4];
    const float* temb     = (const float*)d_in[5];
    const float* remb     = (const float*)d_in[6];
    const float* W1       = (const float*)d_in[7];
    const float* a_src1   = (const float*)d_in[8];
    const float* a_dst1   = (const float*)d_in[9];
    const float* b1       = (const float*)d_in[10];
    const float* ln1_g    = (const float*)d_in[11];
    const float* ln1_b    = (const float*)d_in[12];
    const float* W2       = (const float*)d_in[13];
    const float* a_src2   = (const float*)d_in[14];
    const float* a_dst2   = (const float*)d_in[15];
    const float* b2       = (const float*)d_in[16];
    const float* ln2_g    = (const float*)d_in[17];
    const float* ln2_b    = (const float*)d_in[18];
    const float* Wr1      = (const float*)d_in[19];
    const float* br1      = (const float*)d_in[20];
    const float* Wr2      = (const float*)d_in[21];
    const float* br2      = (const float*)d_in[22];
    float* out = (float*)d_out;

    float *x0, *h1, *s1, *d1, *o1, *x1, *h2, *s2, *d2, *o2, *x2;
    float *p, *clsp, *relp;
    uint32_t *W1H, *W1L, *W2H, *W2L, *WpH, *WpL;
    cudaGetSymbolAddress((void**)&x0,  g_x0);
    cudaGetSymbolAddress((void**)&h1,  g_h1);
    cudaGetSymbolAddress((void**)&s1,  g_s1);
    cudaGetSymbolAddress((void**)&d1,  g_d1);
    cudaGetSymbolAddress((void**)&o1,  g_o1);
    cudaGetSymbolAddress((void**)&x1,  g_x1);
    cudaGetSymbolAddress((void**)&h2,  g_h2);
    cudaGetSymbolAddress((void**)&s2,  g_s2);
    cudaGetSymbolAddress((void**)&d2,  g_d2);
    cudaGetSymbolAddress((void**)&o2,  g_o2);
    cudaGetSymbolAddress((void**)&x2,  g_x2);
    cudaGetSymbolAddress((void**)&p,   g_p);
    cudaGetSymbolAddress((void**)&clsp, g_cls);
    cudaGetSymbolAddress((void**)&relp, g_rel);
    cudaGetSymbolAddress((void**)&W1H, g_W1H);
    cudaGetSymbolAddress((void**)&W1L, g_W1L);
    cudaGetSymbolAddress((void**)&W2H, g_W2H);
    cudaGetSymbolAddress((void**)&W2L, g_W2L);
    cudaGetSymbolAddress((void**)&WpH, g_WpH);
    cudaGetSymbolAddress((void**)&WpL, g_WpL);

    // 0. pre-split weights
    prep_kernel<<<240, 512>>>(W1, W2, Wr1);

    // 1. pooling + type emb
    pool_kernel<<<BB*EE, 256>>>(seq, starts, type_ids, temb, x0);

    // 2. h1 = x0 @ W1
    bf16_gemm_pb<<<dim3(4, 64), 256>>>(x0, W1H, W1L, h1, BB*EE, F1, HH, HH);

    // 3. s1,d1 (warp-per-row)
    sd256_kernel<<<BB*EE/8, 256>>>(h1, a_src1, a_dst1, s1, d1);

    // 4. o1 = softmax(leaky(d+s)) @ h1, per (b,head) — alpha fused
    attn_gemm<<<dim3(2, 2, BB*HEADS1), 256>>>(s1, d1, h1, o1,
                                              DD1, F1, F1, HEADS1,
                                              (long)EE*F1, DD1, (long)EE*F1, DD1);

    // 5. x1 = elu(ln(o1 + b1))
    ln256_kernel<<<BB*EE/8, 256>>>(o1, b1, ln1_g, ln1_b, x1);

    // 6. h2 = x1 @ W2
    bf16_gemm_pb<<<dim3(1, 64), 256>>>(x1, W2H, W2L, h2, BB*EE, DD2, F1, F1);

    // 7. s2,d2
    sd64_kernel<<<BB*EE/8, 256>>>(h2, a_src2, a_dst2, s2, d2);

    // 8. o2 = softmax(leaky(d+s)) @ h2, per b — alpha fused
    attn_gemm<<<dim3(1, 2, BB), 256>>>(s2, d2, h2, o2,
                                       DD2, DD2, DD2, 1,
                                       (long)EE*DD2, 0, (long)EE*DD2, 0);

    // 9. x2 = elu(ln(o2 + b2))
    ln64_kernel<<<BB*EE/8, 256>>>(o2, b2, ln2_g, ln2_b, x2);

    // 10. pair projections: single GEMM (4096,64)@(64,512) -> p=[p1|p2]
    bf16_gemm_pb<<<dim3(8, 64), 256>>>(x2, WpH, WpL, p, BB*EE, 512, DD2, DD2);

    // 11. cls (+br1) and rel projections
    misc_kernel<<<BB + NRR, 256>>>(seq, remb, Wr1, br1, clsp, relp);

    // 12. pair scores
    pair_kernel<<<(BB*PP)/8, 256>>>(pair_idx, rel_ids, p, relp, clsp,
                                    Wr2, br2, out);
}

// round 6
// speedup vs baseline: 1.6269x; 1.0964x over previous
#include <cuda_runtime.h>
#include <cuda_bf16.h>
#include <math.h>
#include <stdint.h>

#define BB 32
#define SS 1024
#define HH 768
#define EE 128
#define WW 8
#define PP 512
#define NTT 5
#define NRR 9
#define DD1 128
#define HEADS1 2
#define DD2 64
#define RDD 32
#define F1 256  // HEADS1*DD1

// ---------------- scratch ----------------
static __device__ float g_x0[BB*EE*HH];
static __device__ float g_h1[BB*EE*F1];
static __device__ float g_s1[BB*HEADS1*EE];
static __device__ float g_d1[BB*HEADS1*EE];
static __device__ float g_o1[BB*EE*F1];
static __device__ float g_x1[BB*EE*F1];
static __device__ float g_h2[BB*EE*DD2];
static __device__ float g_s2[BB*EE];
static __device__ float g_d2[BB*EE];
static __device__ float g_x2[BB*EE*DD2];
static __device__ float g_p[BB*EE*512];      // [row][512] = [p1|p2]
static __device__ float g_cls[BB*256];
static __device__ float g_rel[NRR*256];
// packed bf16 hi/lo weights (pairs along K)
static __device__ uint32_t g_W1H[(HH/2)*F1], g_W1L[(HH/2)*F1];      // 384x256
static __device__ uint32_t g_W2H[(F1/2)*DD2], g_W2L[(F1/2)*DD2];    // 128x64
static __device__ uint32_t g_WpH[(DD2/2)*512], g_WpL[(DD2/2)*512];  // 32x512

// ---------------- bf16 split helpers ----------------
__device__ __forceinline__ void split2(float v0, float v1, uint32_t& h, uint32_t& l) {
    uint32_t hp, lp;
    asm("cvt.rn.bf16x2.f32 %0, %1, %2;" : "=r"(hp) : "f"(v1), "f"(v0));
    float h0 = __uint_as_float(hp << 16);
    float h1 = __uint_as_float(hp & 0xffff0000u);
    asm("cvt.rn.bf16x2.f32 %0, %1, %2;" : "=r"(lp) : "f"(v1 - h1), "f"(v0 - h0));
    h = hp; l = lp;
}
__device__ __forceinline__ void mma16(float* d, const uint32_t* a, const uint32_t* b) {
    asm volatile(
        "mma.sync.aligned.m16n8k16.row.col.f32.bf16.bf16.f32 "
        "{%0,%1,%2,%3},{%4,%5,%6,%7},{%8,%9},{%0,%1,%2,%3};"
        : "+f"(d[0]), "+f"(d[1]), "+f"(d[2]), "+f"(d[3])
        : "r"(a[0]), "r"(a[1]), "r"(a[2]), "r"(a[3]), "r"(b[0]), "r"(b[1]));
}

// ---------------- stage0: prep + zero + pool + misc (one launch) ----------------
#define NB_PREP 480
#define NB_ZERO 96
#define NB_POOL (BB*EE)
#define NB_MISC (BB + NRR)
#define B_ZERO  NB_PREP
#define B_POOL  (B_ZERO + NB_ZERO)
#define B_MISC  (B_POOL + NB_POOL)
#define NB_STAGE0 (B_MISC + NB_MISC)

__global__ __launch_bounds__(256) void stage0_kernel(
        const float* __restrict__ seq,
        const int* __restrict__ starts,
        const int* __restrict__ type_ids,
        const float* __restrict__ temb,
        const float* __restrict__ remb,
        const float* __restrict__ W1,
        const float* __restrict__ W2,
        const float* __restrict__ Wr1,
        const float* __restrict__ br1) {
    __shared__ float4 sbuf4[1730];          // 27.7 KB, aliased per branch
    float* sbuf = (float*)sbuf4;
    int blk = blockIdx.x;
    int t = threadIdx.x;

    if (blk < NB_PREP) {
        // ---- weight pre-split ----
        int idx = blk*256 + t;
        if (idx < 98304) {
            int kp = idx >> 8, n = idx & 255;
            uint32_t h, l;
            split2(W1[(size_t)(2*kp)*F1 + n], W1[(size_t)(2*kp+1)*F1 + n], h, l);
            g_W1H[idx] = h; g_W1L[idx] = l;
        } else if (idx < 106496) {
            int j = idx - 98304;
            int kp = j >> 6, n = j & 63;
            uint32_t h, l;
            split2(W2[(size_t)(2*kp)*DD2 + n], W2[(size_t)(2*kp+1)*DD2 + n], h, l);
            g_W2H[j] = h; g_W2L[j] = l;
        } else {
            int j = idx - 106496;
            int kp = j >> 9, n = j & 511;
            int col = n & 255;
            int base = (n < 256) ? 0 : 64;
            uint32_t h, l;
            split2(Wr1[(size_t)(base + 2*kp)*256 + col],
                   Wr1[(size_t)(base + 2*kp + 1)*256 + col], h, l);
            g_WpH[j] = h; g_WpL[j] = l;
        }
    } else if (blk < B_POOL) {
        // ---- zero s/d accumulators ----
        int j = (blk - B_ZERO)*256 + t;
        if (j < 8192) g_s1[j] = 0.f;
        else if (j < 16384) g_d1[j - 8192] = 0.f;
        else if (j < 20480) g_s2[j - 16384] = 0.f;
        else g_d2[j - 20480] = 0.f;
    } else if (blk < B_MISC) {
        // ---- entity pooling + type embedding ----
        int be = blk - B_POOL;
        int b = be >> 7;
        float* toks = sbuf;
        float* colsum = sbuf + WW*HH;
        float* logits = sbuf + WW*HH + HH;

        int start = starts[be];
        const float4* base4 = (const float4*)(seq + ((size_t)b*SS + start)*HH);
        #pragma unroll
        for (int i = 0; i < 6; i++) sbuf4[t + i*256] = base4[t + i*256];
        __syncthreads();

        for (int h = t; h < HH; h += 256) {
            float cs = 0.f;
            #pragma unroll
            for (int w = 0; w < WW; w++) cs += toks[w*HH + h];
            colsum[h] = cs;
        }
        __syncthreads();

        int warp = t >> 5, lane = t & 31;
        {
            float acc = 0.f;
            for (int h = lane; h < HH; h += 32) acc += toks[warp*HH + h] * colsum[h];
            #pragma unroll
            for (int off = 16; off > 0; off >>= 1) acc += __shfl_xor_sync(0xffffffffu, acc, off);
            if (lane == 0) logits[warp] = acc * 0.125f;
        }
        __syncthreads();

        float m = logits[0];
        #pragma unroll
        for (int w = 1; w < WW; w++) m = fmaxf(m, logits[w]);
        float ex[WW]; float sum = 0.f;
        #pragma unroll
        for (int w = 0; w < WW; w++) { ex[w] = __expf(logits[w] - m); sum += ex[w]; }
        float inv = 1.f / sum;

        int type = type_ids[be];
        const float* te = temb + (size_t)type*HH;
        for (int h = t; h < HH; h += 256) {
            float p = 0.f;
            #pragma unroll
            for (int w = 0; w < WW; w++) p += ex[w] * toks[w*HH + h];
            g_x0[(size_t)be*HH + h] = p*inv + te[h];
        }
    } else {
        // ---- cls (+br1) / rel projections ----
        int mblk = blk - B_MISC;
        int c = t;
        if (mblk < BB) {
            int b = mblk;
            float* cls = sbuf;
            for (int h = c; h < HH; h += 256) cls[h] = seq[(size_t)b*SS*HH + h];
            __syncthreads();
            float acc = br1[c];
            const float* w = Wr1 + (size_t)160*256 + c;
            for (int h = 0; h < HH; h++) acc += cls[h] * w[(size_t)h*256];
            g_cls[b*256 + c] = acc;
        } else {
            int r = mblk - BB;
            float* rv = sbuf;
            if (c < RDD) rv[c] = remb[r*RDD + c];
            __syncthreads();
            float acc = 0.f;
            #pragma unroll
            for (int k = 0; k < RDD; k++) acc += rv[k] * Wr1[(size_t)(128 + k)*256 + c];
            g_rel[r*256 + c] = acc;
        }
    }
}

#define SA 20   // A smem stride (u32)
#define SBp 72  // B smem stride (u32)

// ---------------- GEMM with pre-packed B; optional fused s/d epilogue ----------------
// C[M,N] = A[M,K] @ B[K,N]. If D != 0, also accumulates s/d dots via atomics:
// s_out[(b*Hh+head)*EE+e] += sum_c C[row][c]*a_src[head*D + c%D], head = n0/D.
__global__ __launch_bounds__(256) void bf16_gemm_pb(
        const float* __restrict__ A,
        const uint32_t* __restrict__ BH, const uint32_t* __restrict__ BL,
        float* __restrict__ C, int M, int N, int K, int lda,
        const float* __restrict__ a_src, const float* __restrict__ a_dst,
        float* __restrict__ s_out, float* __restrict__ d_out,
        int D, int Hh) {
    __shared__ uint32_t AsH[64][SA], AsL[64][SA];
    __shared__ uint32_t BsH[16][SBp], BsL[16][SBp];

    int tid = threadIdx.x;
    int wid = tid >> 5, lane = tid & 31;
    int g = lane >> 2, ti = lane & 3;
    int warp_m = wid >> 2, warp_n = wid & 3;
    int m0 = blockIdx.y * 64, n0 = blockIdx.x * 64;

    float acc[2][2][4] = {};

    for (int kc = 0; kc < K; kc += 32) {
        #pragma unroll
        for (int i = 0; i < 2; i++) {
            int idx = tid + i*256;
            int row = idx >> 3, q = idx & 7;
            float4 av = *(const float4*)(A + (size_t)(m0 + row)*lda + kc + q*4);
            uint32_t h0, l0, h1, l1;
            split2(av.x, av.y, h0, l0);
            split2(av.z, av.w, h1, l1);
            AsH[row][2*q]   = h0; AsH[row][2*q+1] = h1;
            AsL[row][2*q]   = l0; AsL[row][2*q+1] = l1;
        }
        {
            int r = tid >> 4;
            int n4 = (tid & 15) * 4;
            size_t off = (size_t)(kc/2 + r)*N + n0 + n4;
            *(uint4*)&BsH[r][n4] = *(const uint4*)(BH + off);
            *(uint4*)&BsL[r][n4] = *(const uint4*)(BL + off);
        }
        __syncthreads();

        #pragma unroll
        for (int s = 0; s < 2; s++) {
            int ab = s*8;
            uint32_t aH[2][4], aL[2][4], bH[2][2], bL[2][2];
            #pragma unroll
            for (int mt = 0; mt < 2; mt++) {
                int rm = warp_m*32 + mt*16;
                aH[mt][0] = AsH[rm + g    ][ab + ti    ];
                aH[mt][1] = AsH[rm + g + 8][ab + ti    ];
                aH[mt][2] = AsH[rm + g    ][ab + ti + 4];
                aH[mt][3] = AsH[rm + g + 8][ab + ti + 4];
                aL[mt][0] = AsL[rm + g    ][ab + ti    ];
                aL[mt][1] = AsL[rm + g + 8][ab + ti    ];
                aL[mt][2] = AsL[rm + g    ][ab + ti + 4];
                aL[mt][3] = AsL[rm + g + 8][ab + ti + 4];
            }
            #pragma unroll
            for (int nt = 0; nt < 2; nt++) {
                int cn = warp_n*16 + nt*8;
                bH[nt][0] = BsH[ab + ti    ][cn + g];
                bH[nt][1] = BsH[ab + ti + 4][cn + g];
                bL[nt][0] = BsL[ab + ti    ][cn + g];
                bL[nt][1] = BsL[ab + ti + 4][cn + g];
            }
            #pragma unroll
            for (int mt = 0; mt < 2; mt++)
                #pragma unroll
                for (int nt = 0; nt < 2; nt++) {
                    mma16(acc[mt][nt], aH[mt], bL[nt]);
                    mma16(acc[mt][nt], aL[mt], bH[nt]);
                    mma16(acc[mt][nt], aH[mt], bH[nt]);
                }
        }
        __syncthreads();
    }

    #pragma unroll
    for (int mt = 0; mt < 2; mt++) {
        int rm = m0 + warp_m*32 + mt*16;
        #pragma unroll
        for (int nt = 0; nt < 2; nt++) {
            int cn = n0 + warp_n*16 + nt*8;
            float* c0 = C + (size_t)(rm + g)*N + cn + 2*ti;
            float* c2 = C + (size_t)(rm + g + 8)*N + cn + 2*ti;
            c0[0] = acc[mt][nt][0]; c0[1] = acc[mt][nt][1];
            c2[0] = acc[mt][nt][2]; c2[1] = acc[mt][nt][3];
        }
    }

    // ---- fused s/d dot epilogue ----
    if (D) {
        int head = n0 / D;
        const float* as = a_src + head*D;
        const float* ad = a_dst + head*D;
        int cbase = n0 & (D-1);
        float sv[4] = {0.f,0.f,0.f,0.f}, dv[4] = {0.f,0.f,0.f,0.f};
        #pragma unroll
        for (int nt = 0; nt < 2; nt++) {
            int c = cbase + warp_n*16 + nt*8 + 2*ti;
            float w0s = as[c], w1s = as[c+1];
            float w0d = ad[c], w1d = ad[c+1];
            #pragma unroll
            for (int mt = 0; mt < 2; mt++) {
                sv[mt*2+0] += acc[mt][nt][0]*w0s + acc[mt][nt][1]*w1s;
                sv[mt*2+1] += acc[mt][nt][2]*w0s + acc[mt][nt][3]*w1s;
                dv[mt*2+0] += acc[mt][nt][0]*w0d + acc[mt][nt][1]*w1d;
                dv[mt*2+1] += acc[mt][nt][2]*w0d + acc[mt][nt][3]*w1d;
            }
        }
        #pragma unroll
        for (int i = 0; i < 4; i++) {
            sv[i] += __shfl_xor_sync(0xffffffffu, sv[i], 1);
            sv[i] += __shfl_xor_sync(0xffffffffu, sv[i], 2);
            dv[i] += __shfl_xor_sync(0xffffffffu, dv[i], 1);
            dv[i] += __shfl_xor_sync(0xffffffffu, dv[i], 2);
        }
        if (ti == 0) {
            #pragma unroll
            for (int mt = 0; mt < 2; mt++)
                #pragma unroll
                for (int rr = 0; rr < 2; rr++) {
                    int grow = m0 + warp_m*32 + mt*16 + rr*8 + g;
                    int b = grow >> 7, e = grow & 127;
                    int idx = (b*Hh + head)*EE + e;
                    atomicAdd(&s_out[idx], sv[mt*2+rr]);
                    atomicAdd(&d_out[idx], dv[mt*2+rr]);
                }
        }
    }
}

// ---------------- attention GEMM: C = softmax_rows(leaky(d_i+s_j)) @ B ----------------
// K = EE = 128 fixed. If lnbias != nullptr (requires gridDim.x==1, N==64):
// fused bias+layernorm+elu epilogue writing xout instead of C.
__global__ __launch_bounds__(256) void attn_gemm(
        const float* __restrict__ s_in, const float* __restrict__ d_in,
        const float* __restrict__ Bm, float* __restrict__ C,
        int N, int ldb, int ldc,
        int Hh, long sBb, long sBh, long sCb, long sCh,
        const float* __restrict__ lnbias, const float* __restrict__ lng,
        const float* __restrict__ lnbt, float* __restrict__ xout) {
    int bz = blockIdx.z;
    int bb = bz / Hh, hh = bz - bb*Hh;
    const float* sp = s_in + (size_t)bz*EE;
    const float* dp = d_in + (size_t)bz*EE;
    Bm += (long)bb * sBb + (long)hh * sBh;
    C  += (long)bb * sCb + (long)hh * sCh;

    __shared__ uint32_t AsH[64][SA], AsL[64][SA];
    __shared__ uint32_t BsH[16][SBp], BsL[16][SBp];
    __shared__ float s_sh[EE], d_sh[64], m_sh[64], inv_sh[64];
    __shared__ float Cs[64][68];

    int tid = threadIdx.x;
    int wid = tid >> 5, lane = tid & 31;
    int g = lane >> 2, ti = lane & 3;
    int warp_m = wid >> 2, warp_n = wid & 3;
    int m0 = blockIdx.y * 64, n0 = blockIdx.x * 64;

    if (tid < EE) s_sh[tid] = sp[tid];
    else if (tid < EE + 64) d_sh[tid - EE] = dp[m0 + tid - EE];
    __syncthreads();

    #pragma unroll
    for (int rr = 0; rr < 8; rr++) {
        int i = wid*8 + rr;
        float di = d_sh[i];
        float ev[4]; float m = -1e30f;
        #pragma unroll
        for (int q = 0; q < 4; q++) {
            float e = di + s_sh[lane + q*32];
            e = fmaxf(e, 0.2f*e);
            ev[q] = e;
            m = fmaxf(m, e);
        }
        #pragma unroll
        for (int off = 16; off > 0; off >>= 1) m = fmaxf(m, __shfl_xor_sync(0xffffffffu, m, off));
        float sum = 0.f;
        #pragma unroll
        for (int q = 0; q < 4; q++) sum += __expf(ev[q] - m);
        #pragma unroll
        for (int off = 16; off > 0; off >>= 1) sum += __shfl_xor_sync(0xffffffffu, sum, off);
        if (lane == 0) { m_sh[i] = m; inv_sh[i] = 1.f / sum; }
    }
    __syncthreads();

    float acc[2][2][4] = {};

    for (int kc = 0; kc < EE; kc += 32) {
        #pragma unroll
        for (int i = 0; i < 2; i++) {
            int idx = tid + i*256;
            int row = idx >> 3, q = idx & 7;
            float di = d_sh[row], mi = m_sh[row], ii = inv_sh[row];
            float v[4];
            #pragma unroll
            for (int tq = 0; tq < 4; tq++) {
                float e = di + s_sh[kc + 4*q + tq];
                e = fmaxf(e, 0.2f*e);
                v[tq] = __expf(e - mi) * ii;
            }
            uint32_t h0, l0, h1, l1;
            split2(v[0], v[1], h0, l0);
            split2(v[2], v[3], h1, l1);
            AsH[row][2*q]   = h0; AsH[row][2*q+1] = h1;
            AsL[row][2*q]   = l0; AsL[row][2*q+1] = l1;
        }
        {
            int r = tid >> 4;
            int n4 = (tid & 15) * 4;
            float4 b0v = *(const float4*)(Bm + (size_t)(kc + 2*r)*ldb + n0 + n4);
            float4 b1v = *(const float4*)(Bm + (size_t)(kc + 2*r + 1)*ldb + n0 + n4);
            uint32_t h, l;
            split2(b0v.x, b1v.x, h, l); BsH[r][n4+0] = h; BsL[r][n4+0] = l;
            split2(b0v.y, b1v.y, h, l); BsH[r][n4+1] = h; BsL[r][n4+1] = l;
            split2(b0v.z, b1v.z, h, l); BsH[r][n4+2] = h; BsL[r][n4+2] = l;
            split2(b0v.w, b1v.w, h, l); BsH[r][n4+3] = h; BsL[r][n4+3] = l;
        }
        __syncthreads();

        #pragma unroll
        for (int s = 0; s < 2; s++) {
            int ab = s*8;
            uint32_t aH[2][4], aL[2][4], bH[2][2], bL[2][2];
            #pragma unroll
            for (int mt = 0; mt < 2; mt++) {
                int rm = warp_m*32 + mt*16;
                aH[mt][0] = AsH[rm + g    ][ab + ti    ];
                aH[mt][1] = AsH[rm + g + 8][ab + ti    ];
                aH[mt][2] = AsH[rm + g    ][ab + ti + 4];
                aH[mt][3] = AsH[rm + g + 8][ab + ti + 4];
                aL[mt][0] = AsL[rm + g    ][ab + ti    ];
                aL[mt][1] = AsL[rm + g + 8][ab + ti    ];
                aL[mt][2] = AsL[rm + g    ][ab + ti + 4];
                aL[mt][3] = AsL[rm + g + 8][ab + ti + 4];
            }
            #pragma unroll
            for (int nt = 0; nt < 2; nt++) {
                int cn = warp_n*16 + nt*8;
                bH[nt][0] = BsH[ab + ti    ][cn + g];
                bH[nt][1] = BsH[ab + ti + 4][cn + g];
                bL[nt][0] = BsL[ab + ti    ][cn + g];
                bL[nt][1] = BsL[ab + ti + 4][cn + g];
            }
            #pragma unroll
            for (int mt = 0; mt < 2; mt++)
                #pragma unroll
                for (int nt = 0; nt < 2; nt++) {
                    mma16(acc[mt][nt], aH[mt], bL[nt]);
                    mma16(acc[mt][nt], aL[mt], bH[nt]);
                    mma16(acc[mt][nt], aH[mt], bH[nt]);
                }
        }
        __syncthreads();
    }

    if (lnbias == nullptr) {
        #pragma unroll
        for (int mt = 0; mt < 2; mt++) {
            int rm = m0 + warp_m*32 + mt*16;
            #pragma unroll
            for (int nt = 0; nt < 2; nt++) {
                int cn = n0 + warp_n*16 + nt*8;
                float* c0 = C + (size_t)(rm + g)*ldc + cn + 2*ti;
                float* c2 = C + (size_t)(rm + g + 8)*ldc + cn + 2*ti;
                c0[0] = acc[mt][nt][0]; c0[1] = acc[mt][nt][1];
                c2[0] = acc[mt][nt][2]; c2[1] = acc[mt][nt][3];
            }
        }
    } else {
        // fused bias + layernorm + elu (N == 64, full row in block)
        #pragma unroll
        for (int mt = 0; mt < 2; mt++) {
            int r0 = warp_m*32 + mt*16 + g;
            #pragma unroll
            for (int nt = 0; nt < 2; nt++) {
                int cn = warp_n*16 + nt*8 + 2*ti;
                Cs[r0    ][cn] = acc[mt][nt][0]; Cs[r0    ][cn+1] = acc[mt][nt][1];
                Cs[r0 + 8][cn] = acc[mt][nt][2]; Cs[r0 + 8][cn+1] = acc[mt][nt][3];
            }
        }
        __syncthreads();
        int c = 2*lane;
        float2 bb2 = *(const float2*)(lnbias + c);
        float2 gg  = *(const float2*)(lng + c);
        float2 tt  = *(const float2*)(lnbt + c);
        #pragma unroll
        for (int rr = 0; rr < 8; rr++) {
            int r = wid*8 + rr;
            float vx = Cs[r][c]   + bb2.x;
            float vy = Cs[r][c+1] + bb2.y;
            float s = vx + vy, s2 = vx*vx + vy*vy;
            #pragma unroll
            for (int off = 16; off > 0; off >>= 1) {
                s  += __shfl_xor_sync(0xffffffffu, s,  off);
                s2 += __shfl_xor_sync(0xffffffffu, s2, off);
            }
            float mean = s * (1.f/64.f);
            float var  = s2 * (1.f/64.f) - mean*mean;
            float rstd = rsqrtf(var + 1e-5f);
            float ox = (vx - mean)*rstd*gg.x + tt.x;
            float oy = (vy - mean)*rstd*gg.y + tt.y;
            ox = ox > 0.f ? ox : expm1f(ox);
            oy = oy > 0.f ? oy : expm1f(oy);
            float2 o2v = make_float2(ox, oy);
            *(float2*)(xout + (size_t)(bz*EE + m0 + r)*64 + c) = o2v;
        }
    }
}

// ---------------- bias + layernorm + elu (256-wide rows), warp-per-row ----------------
__global__ void ln256_kernel(const float* __restrict__ in,
                             const float* __restrict__ bias,
                             const float* __restrict__ g,
                             const float* __restrict__ bt,
                             float* __restrict__ out) {
    int t = threadIdx.x;
    int row = blockIdx.x*8 + (t >> 5);
    int lane = t & 31;
    int c0 = 4*lane, c1 = 128 + 4*lane;
    const float* ir = in + (size_t)row*256;
    float4 v0 = *(const float4*)(ir + c0);
    float4 v1 = *(const float4*)(ir + c1);
    float4 b0 = *(const float4*)(bias + c0);
    float4 b1 = *(const float4*)(bias + c1);
    v0.x += b0.x; v0.y += b0.y; v0.z += b0.z; v0.w += b0.w;
    v1.x += b1.x; v1.y += b1.y; v1.z += b1.z; v1.w += b1.w;
    float s  = v0.x+v0.y+v0.z+v0.w + v1.x+v1.y+v1.z+v1.w;
    float s2 = v0.x*v0.x+v0.y*v0.y+v0.z*v0.z+v0.w*v0.w
             + v1.x*v1.x+v1.y*v1.y+v1.z*v1.z+v1.w*v1.w;
    #pragma unroll
    for (int off = 16; off > 0; off >>= 1) {
        s  += __shfl_xor_sync(0xffffffffu, s,  off);
        s2 += __shfl_xor_sync(0xffffffffu, s2, off);
    }
    float mean = s * (1.f/256.f);
    float var  = s2 * (1.f/256.f) - mean*mean;
    float r = rsqrtf(var + 1e-5f);
    float4 g0 = *(const float4*)(g + c0);
    float4 g1 = *(const float4*)(g + c1);
    float4 t0 = *(const float4*)(bt + c0);
    float4 t1 = *(const float4*)(bt + c1);
    float4 o0, o1;
    o0.x = (v0.x-mean)*r*g0.x + t0.x; o0.y = (v0.y-mean)*r*g0.y + t0.y;
    o0.z = (v0.z-mean)*r*g0.z + t0.z; o0.w = (v0.w-mean)*r*g0.w + t0.w;
    o1.x = (v1.x-mean)*r*g1.x + t1.x; o1.y = (v1.y-mean)*r*g1.y + t1.y;
    o1.z = (v1.z-mean)*r*g1.z + t1.z; o1.w = (v1.w-mean)*r*g1.w + t1.w;
    o0.x = o0.x > 0.f ? o0.x : expm1f(o0.x); o0.y = o0.y > 0.f ? o0.y : expm1f(o0.y);
    o0.z = o0.z > 0.f ? o0.z : expm1f(o0.z); o0.w = o0.w > 0.f ? o0.w : expm1f(o0.w);
    o1.x = o1.x > 0.f ? o1.x : expm1f(o1.x); o1.y = o1.y > 0.f ? o1.y : expm1f(o1.y);
    o1.z = o1.z > 0.f ? o1.z : expm1f(o1.z); o1.w = o1.w > 0.f ? o1.w : expm1f(o1.w);
    float* orow = out + (size_t)row*256;
    *(float4*)(orow + c0) = o0;
    *(float4*)(orow + c1) = o1;
}

// ---------------- final pair scores ----------------
__global__ void pair_kernel(const int* __restrict__ pidx,
                            const int* __restrict__ rids,
                            const float* __restrict__ p,
                            const float* __restrict__ relp,
                            const float* __restrict__ clsp,
                            const float* __restrict__ Wr2,
                            const float* __restrict__ br2,
                            float* __restrict__ out) {
    int g = (blockIdx.x * blockDim.x + threadIdx.x) >> 5;
    int lane = threadIdx.x & 31;
    int b = g / PP, pp = g % PP;
    int pi = pidx[(b*PP + pp)*2 + 0];
    int pj = pidx[(b*PP + pp)*2 + 1];
    int r  = rids[b*PP + pp];
    const float* a1 = p + (size_t)(b*EE + pi)*512;
    const float* a2 = p + (size_t)(b*EE + pj)*512 + 256;
    const float* ar = relp + r*256;
    const float* ac = clsp + b*256;
    float acc = 0.f;
    #pragma unroll
    for (int q = 0; q < 8; q++) {
        int c = lane + q*32;
        float v = a1[c] + a2[c] + ar[c] + ac[c];
        v = fmaxf(v, 0.f);
        acc += v * Wr2[c];
    }
    #pragma unroll
    for (int off = 16; off > 0; off >>= 1) acc += __shfl_xor_sync(0xffffffffu, acc, off);
    if (lane == 0) out[b*PP + pp] = acc + br2[0];
}

// ---------------- launch ----------------
extern "C" void kernel_launch(void* const* d_in, const int* in_sizes, int n_in,
                              void* d_out, int out_size) {
    const float* seq      = (const float*)d_in[0];
    const int*   starts   = (const int*)  d_in[1];
    const int*   type_ids = (const int*)  d_in[2];
    const int*   pair_idx = (const int*)  d_in[3];
    const int*   rel_ids  = (const int*)  d_in[4];
    const float* temb     = (const float*)d_in[5];
    const float* remb     = (const float*)d_in[6];
    const float* W1       = (const float*)d_in[7];
    const float* a_src1   = (const float*)d_in[8];
    const float* a_dst1   = (const float*)d_in[9];
    const float* b1       = (const float*)d_in[10];
    const float* ln1_g    = (const float*)d_in[11];
    const float* ln1_b    = (const float*)d_in[12];
    const float* W2       = (const float*)d_in[13];
    const float* a_src2   = (const float*)d_in[14];
    const float* a_dst2   = (const float*)d_in[15];
    const float* b2       = (const float*)d_in[16];
    const float* ln2_g    = (const float*)d_in[17];
    const float* ln2_b    = (const float*)d_in[18];
    const float* Wr1      = (const float*)d_in[19];
    const float* br1      = (const float*)d_in[20];
    const float* Wr2      = (const float*)d_in[21];
    const float* br2      = (const float*)d_in[22];
    float* out = (float*)d_out;

    float *x0, *h1, *s1, *d1, *o1, *x1, *h2, *s2, *d2, *x2, *p, *clsp, *relp;
    uint32_t *W1H, *W1L, *W2H, *W2L, *WpH, *WpL;
    cudaGetSymbolAddress((void**)&x0,  g_x0);
    cudaGetSymbolAddress((void**)&h1,  g_h1);
    cudaGetSymbolAddress((void**)&s1,  g_s1);
    cudaGetSymbolAddress((void**)&d1,  g_d1);
    cudaGetSymbolAddress((void**)&o1,  g_o1);
    cudaGetSymbolAddress((void**)&x1,  g_x1);
    cudaGetSymbolAddress((void**)&h2,  g_h2);
    cudaGetSymbolAddress((void**)&s2,  g_s2);
    cudaGetSymbolAddress((void**)&d2,  g_d2);
    cudaGetSymbolAddress((void**)&x2,  g_x2);
    cudaGetSymbolAddress((void**)&p,   g_p);
    cudaGetSymbolAddress((void**)&clsp, g_cls);
    cudaGetSymbolAddress((void**)&relp, g_rel);
    cudaGetSymbolAddress((void**)&W1H, g_W1H);
    cudaGetSymbolAddress((void**)&W1L, g_W1L);
    cudaGetSymbolAddress((void**)&W2H, g_W2H);
    cudaGetSymbolAddress((void**)&W2L, g_W2L);
    cudaGetSymbolAddress((void**)&WpH, g_WpH);
    cudaGetSymbolAddress((void**)&WpL, g_WpL);

    // 1. stage0: prep + zero + pool + misc (one launch)
    stage0_kernel<<<NB_STAGE0, 256>>>(seq, starts, type_ids, temb, remb,
                                      W1, W2, Wr1, br1);

    // 2. h1 = x0 @ W1, s1/d1 fused (atomics)
    bf16_gemm_pb<<<dim3(4, 64), 256>>>(x0, W1H, W1L, h1, BB*EE, F1, HH, HH,
                                       a_src1, a_dst1, s1, d1, DD1, HEADS1);

    // 3. o1 = softmax(leaky(d+s)) @ h1, per (b,head)
    attn_gemm<<<dim3(2, 2, BB*HEADS1), 256>>>(s1, d1, h1, o1,
                                              DD1, F1, F1, HEADS1,
                                              (long)EE*F1, DD1, (long)EE*F1, DD1,
                                              nullptr, nullptr, nullptr, nullptr);

    // 4. x1 = elu(ln(o1 + b1))
    ln256_kernel<<<BB*EE/8, 256>>>(o1, b1, ln1_g, ln1_b, x1);

    // 5. h2 = x1 @ W2, s2/d2 fused
    bf16_gemm_pb<<<dim3(1, 64), 256>>>(x1, W2H, W2L, h2, BB*EE, DD2, F1, F1,
                                       a_src2, a_dst2, s2, d2, DD2, 1);

    // 6. x2 = elu(ln(softmax @ h2 + b2)) — attn + LN fused, writes x2 directly
    attn_gemm<<<dim3(1, 2, BB), 256>>>(s2, d2, h2, x2,
                                       DD2, DD2, DD2, 1,
                                       (long)EE*DD2, 0, (long)EE*DD2, 0,
                                       b2, ln2_g, ln2_b, x2);

    // 7. pair projections: (4096,64)@(64,512) -> p=[p1|p2]
    bf16_gemm_pb<<<dim3(8, 64), 256>>>(x2, WpH, WpL, p, BB*EE, 512, DD2, DD2,
                                       nullptr, nullptr, nullptr, nullptr, 0, 1);

    // 8. pair scores
    pair_kernel<<<(BB*PP)/8, 256>>>(pair_idx, rel_ids, p, relp, clsp,
                                    Wr2, br2, out);
}